// round 4
// baseline (speedup 1.0000x reference)
#include <cuda_runtime.h>
#include <cstdint>

#define N_LAT 4096
#define N_QRY 16384
#define BB    4
#define CIN   64

// ---------------- scratch (device globals: allocation-free rule) ----------------
__device__ float g_acc[2 * BB * N_QRY * CIN];   // [scale][b][q][c], 33.5 MB
__device__ float g_cnt[2 * N_QRY];              // edge counts per query per scale
__device__ float g_w[N_QRY * 2];                // softmax switch weights

// ---------------- packed f32x2 helpers (FFMA2 — PTX-only on sm_103a) ------------
__device__ __forceinline__ unsigned long long fma2(unsigned long long a,
                                                   unsigned long long b,
                                                   unsigned long long c) {
    unsigned long long d;
    asm("fma.rn.f32x2 %0, %1, %2, %3;" : "=l"(d) : "l"(a), "l"(b), "l"(c));
    return d;
}
__device__ __forceinline__ unsigned long long dup2(float x) {
    unsigned long long r;
    asm("mov.b64 %0, {%1, %1};" : "=l"(r) : "f"(x));
    return r;
}
__device__ __forceinline__ float2 unpk2(unsigned long long v) {
    float2 r;
    asm("mov.b64 {%0, %1}, %2;" : "=f"(r.x), "=f"(r.y) : "l"(v));
    return r;
}

// ---------------- gelu (tanh approximation, matches jax.nn.gelu default) --------
__device__ __forceinline__ float gelu_f(float x) {
    float x2 = x * x;
    float y  = 0.7978845608028654f * x * fmaf(0.044715f, x2, 1.0f);
    float e  = __expf(2.0f * y);                 // MUFU.EX2 path
    float t  = 1.0f - __fdividef(2.0f, e + 1.0f); // == tanh(y)
    return 0.5f * x * (1.0f + t);
}

// ---------------- kernel 0: zero accumulators -----------------------------------
__global__ void zero_kernel() {
    const size_t n4 = (size_t)(2 * BB * N_QRY * CIN) / 4;
    float4* p = (float4*)g_acc;
    const float4 z = make_float4(0.f, 0.f, 0.f, 0.f);
    for (size_t i = (size_t)blockIdx.x * blockDim.x + threadIdx.x; i < n4;
         i += (size_t)gridDim.x * blockDim.x)
        p[i] = z;
    for (int i = blockIdx.x * blockDim.x + threadIdx.x; i < 2 * N_QRY;
         i += gridDim.x * blockDim.x)
        g_cnt[i] = 0.f;
}

// ---------------- kernel 1: switch MLP + softmax --------------------------------
__global__ void switch_kernel(const float* __restrict__ qc,
                              const float* __restrict__ Wsw0, const float* __restrict__ bsw0,
                              const float* __restrict__ Wsw1, const float* __restrict__ bsw1) {
    int q = blockIdx.x * blockDim.x + threadIdx.x;
    if (q >= N_QRY) return;
    float x0 = qc[2 * q], x1 = qc[2 * q + 1];
    float l0 = bsw1[0], l1 = bsw1[1];
#pragma unroll
    for (int j = 0; j < 16; j++) {
        float hv = bsw0[j];
        hv = fmaf(x0, Wsw0[j], hv);
        hv = fmaf(x1, Wsw0[16 + j], hv);
        hv = fmaxf(hv, 0.f);
        l0 = fmaf(hv, Wsw1[2 * j], l0);
        l1 = fmaf(hv, Wsw1[2 * j + 1], l1);
    }
    float m = fmaxf(l0, l1);
    float e0 = expf(l0 - m), e1 = expf(l1 - m);
    float inv = 1.f / (e0 + e1);
    g_w[2 * q]     = e0 * inv;
    g_w[2 * q + 1] = e1 * inv;
}

// ---------------- kernel 2: per-edge MLP (tiled FFMA2 GEMM) + seg reduction ------
// Layer 1: thread = edge (tiny 4->64).
// Layers 2/3: block GEMM [128 edges x 64] @ [64 x 64]; thread tile = 4 edges x 16
//   outputs. Weight LDS.128 (warp-uniform broadcast) + activation LDS.128 reused
//   across the register tile -> ~5 LDS.128 per 64 MACs, 32 FFMA2 per k.
// Phase B: sorted-run segmented reduction with boundary atomics (unchanged).
#define EPB 128
#define STRIDE 68
#define OW0T 0
#define OB0  256
#define OB1  320
#define OB2  384
#define OW1  448
#define OW2  4544
#define OIDX 8640
#define OBUFA 8896
#define OBUFB 17600
#define SMEM_EDGE_FLOATS (OBUFB + EPB * STRIDE)   // 26304 floats = 105216 B

__device__ __forceinline__ float f4c(const float4& v, int kk) {
    return kk == 0 ? v.x : (kk == 1 ? v.y : (kk == 2 ? v.z : v.w));
}

__device__ __forceinline__ void layer_tiled(float* sm, int srcOfs, int dstOfs,
                                            int wOfs, int bOfs,
                                            int jh, int lane, bool act) {
    unsigned long long acc[4][8];
    {
        const unsigned long long* bini = (const unsigned long long*)(sm + bOfs + jh * 16);
#pragma unroll
        for (int p = 0; p < 8; p++) {
            unsigned long long b = bini[p];
            acc[0][p] = b; acc[1][p] = b; acc[2][p] = b; acc[3][p] = b;
        }
    }
    const float* s0 = sm + srcOfs + lane * STRIDE;
    const float* wbase = sm + wOfs + jh * 16;
#pragma unroll 1
    for (int kq = 0; kq < 16; kq++) {
        float4 a0 = *(const float4*)(s0 + 0  * STRIDE + kq * 4);
        float4 a1 = *(const float4*)(s0 + 32 * STRIDE + kq * 4);
        float4 a2 = *(const float4*)(s0 + 64 * STRIDE + kq * 4);
        float4 a3 = *(const float4*)(s0 + 96 * STRIDE + kq * 4);
#pragma unroll
        for (int kk = 0; kk < 4; kk++) {
            const ulonglong2* wp = (const ulonglong2*)(wbase + (kq * 4 + kk) * 64);
            ulonglong2 wA = wp[0];
            ulonglong2 wB = wp[1];
            unsigned long long d0 = dup2(f4c(a0, kk));
            unsigned long long d1 = dup2(f4c(a1, kk));
            unsigned long long d2 = dup2(f4c(a2, kk));
            unsigned long long d3 = dup2(f4c(a3, kk));
            acc[0][0] = fma2(d0, wA.x, acc[0][0]); acc[0][1] = fma2(d0, wA.y, acc[0][1]);
            acc[1][0] = fma2(d1, wA.x, acc[1][0]); acc[1][1] = fma2(d1, wA.y, acc[1][1]);
            acc[2][0] = fma2(d2, wA.x, acc[2][0]); acc[2][1] = fma2(d2, wA.y, acc[2][1]);
            acc[3][0] = fma2(d3, wA.x, acc[3][0]); acc[3][1] = fma2(d3, wA.y, acc[3][1]);
            acc[0][2] = fma2(d0, wB.x, acc[0][2]); acc[0][3] = fma2(d0, wB.y, acc[0][3]);
            acc[1][2] = fma2(d1, wB.x, acc[1][2]); acc[1][3] = fma2(d1, wB.y, acc[1][3]);
            acc[2][2] = fma2(d2, wB.x, acc[2][2]); acc[2][3] = fma2(d2, wB.y, acc[2][3]);
            acc[3][2] = fma2(d3, wB.x, acc[3][2]); acc[3][3] = fma2(d3, wB.y, acc[3][3]);
            ulonglong2 wC = wp[2];
            ulonglong2 wD = wp[3];
            acc[0][4] = fma2(d0, wC.x, acc[0][4]); acc[0][5] = fma2(d0, wC.y, acc[0][5]);
            acc[1][4] = fma2(d1, wC.x, acc[1][4]); acc[1][5] = fma2(d1, wC.y, acc[1][5]);
            acc[2][4] = fma2(d2, wC.x, acc[2][4]); acc[2][5] = fma2(d2, wC.y, acc[2][5]);
            acc[3][4] = fma2(d3, wC.x, acc[3][4]); acc[3][5] = fma2(d3, wC.y, acc[3][5]);
            acc[0][6] = fma2(d0, wD.x, acc[0][6]); acc[0][7] = fma2(d0, wD.y, acc[0][7]);
            acc[1][6] = fma2(d1, wD.x, acc[1][6]); acc[1][7] = fma2(d1, wD.y, acc[1][7]);
            acc[2][6] = fma2(d2, wD.x, acc[2][6]); acc[2][7] = fma2(d2, wD.y, acc[2][7]);
            acc[3][6] = fma2(d3, wD.x, acc[3][6]); acc[3][7] = fma2(d3, wD.y, acc[3][7]);
        }
    }
#pragma unroll
    for (int e = 0; e < 4; e++) {
        float* drow = sm + dstOfs + (lane + 32 * e) * STRIDE + jh * 16;
#pragma unroll
        for (int m = 0; m < 4; m++) {
            float2 v0 = unpk2(acc[e][2 * m]);
            float2 v1 = unpk2(acc[e][2 * m + 1]);
            float4 o;
            if (act) {
                o.x = gelu_f(v0.x); o.y = gelu_f(v0.y);
                o.z = gelu_f(v1.x); o.w = gelu_f(v1.y);
            } else {
                o.x = v0.x; o.y = v0.y; o.z = v1.x; o.w = v1.y;
            }
            *(float4*)(drow + 4 * m) = o;
        }
    }
}

__global__ __launch_bounds__(128, 2) void edge_kernel(
    const float* __restrict__ latc, const float* __restrict__ qc,
    const float* __restrict__ rnd,
    const int* __restrict__ src, const int* __restrict__ qry,
    const float* __restrict__ Wk0, const float* __restrict__ bk0,
    const float* __restrict__ Wk1, const float* __restrict__ bk1,
    const float* __restrict__ Wk2, const float* __restrict__ bk2,
    int scale, int E)
{
    extern __shared__ float sm[];
    const int tid = threadIdx.x;

    // cooperative weight staging (W0 transposed for float4 reads)
    for (int i = tid; i < 256; i += 128) sm[OW0T + (i & 63) * 4 + (i >> 6)] = Wk0[i];
    if (tid < 64) { sm[OB0 + tid] = bk0[tid]; sm[OB1 + tid] = bk1[tid]; sm[OB2 + tid] = bk2[tid]; }
    for (int i = tid; i < 4096; i += 128) { sm[OW1 + i] = Wk1[i]; sm[OW2 + i] = Wk2[i]; }

    const int e = blockIdx.x * EPB + tid;
    int s = 0, q = -1;
    if (e < E) { s = src[e]; q = qry[e]; }
    int* sidx = (int*)(sm + OIDX);
    sidx[tid] = s;
    sidx[EPB + tid] = q;
    float f0 = latc[2 * s], f1 = latc[2 * s + 1];
    float f2 = 0.f, f3 = 0.f;
    if (q >= 0) { f2 = qc[2 * q]; f3 = qc[2 * q + 1]; }
    __syncthreads();

    // layer 1: 4 -> 64 (thread = edge), gelu, write own bufA row
    {
        const float4* w0 = (const float4*)(sm + OW0T);
        float* rowA = sm + OBUFA + tid * STRIDE;
#pragma unroll
        for (int j4 = 0; j4 < 16; j4++) {
            float4 o;
#pragma unroll
            for (int jj = 0; jj < 4; jj++) {
                int j = j4 * 4 + jj;
                float4 w = w0[j];
                float a = sm[OB0 + j];
                a = fmaf(f0, w.x, a); a = fmaf(f1, w.y, a);
                a = fmaf(f2, w.z, a); a = fmaf(f3, w.w, a);
                float g = gelu_f(a);
                if (jj == 0) o.x = g; else if (jj == 1) o.y = g;
                else if (jj == 2) o.z = g; else o.w = g;
            }
            *(float4*)(rowA + j4 * 4) = o;
        }
    }
    __syncthreads();

    const int lane = tid & 31;
    const int jh = tid >> 5;
    // layer 2: 64 -> 64, gelu, bufA -> bufB
    layer_tiled(sm, OBUFA, OBUFB, OW1, OB1, jh, lane, true);
    __syncthreads();
    // layer 3: 64 -> 64, no act, bufB -> bufA (final k)
    layer_tiled(sm, OBUFB, OBUFA, OW2, OB2, jh, lane, false);
    __syncthreads();

    // ---- phase B: segmented reduction over the 128 sorted edges ----
    const int b  = tid >> 5;
    const int c2 = tid & 31;
    const float* rb = rnd + (size_t)b * N_LAT * CIN + 2 * c2;
    float* accBase = g_acc + ((size_t)(scale * BB + b) * N_QRY) * CIN + 2 * c2;
    float* cntBase = g_cnt + scale * N_QRY;

    float ax = 0.f, ay = 0.f;
    int prevq = -1, run = 0;
#pragma unroll 2
    for (int el = 0; el < EPB; el++) {
        int qq = sidx[EPB + el];
        if (qq != prevq) {
            if (prevq >= 0) {
                float* d = accBase + (size_t)prevq * CIN;
                atomicAdd(d, ax);
                atomicAdd(d + 1, ay);
                if (tid == 0) atomicAdd(cntBase + prevq, (float)run);
            }
            ax = 0.f; ay = 0.f; run = 0; prevq = qq;
        }
        if (qq >= 0) {
            int ss = sidx[el];
            float2 kk = *(const float2*)(sm + OBUFA + el * STRIDE + 2 * c2);
            float2 rr = *(const float2*)(rb + (size_t)ss * CIN);
            ax = fmaf(kk.x, rr.x, ax);
            ay = fmaf(kk.y, rr.y, ay);
            run++;
        }
    }
    if (prevq >= 0) {
        float* d = accBase + (size_t)prevq * CIN;
        atomicAdd(d, ax);
        atomicAdd(d + 1, ay);
        if (tid == 0) atomicAdd(cntBase + prevq, (float)run);
    }
}

// ---------------- kernel 3: combine scales + projection MLP ----------------------
#define OCWP0 0
#define OCBP0 16384
#define OCWP1 16640
#define OCBP1 17664
#define OCDEC 17668
#define SMEM_COMB_FLOATS (OCDEC + 8 * 64)  // 18180 floats = 72720 B
#define CTASKS 8

__global__ __launch_bounds__(256) void combine_kernel(
    const float* __restrict__ Wp0, const float* __restrict__ bp0,
    const float* __restrict__ Wp1, const float* __restrict__ bp1,
    float* __restrict__ out)
{
    extern __shared__ float sm[];
    const int tid = threadIdx.x;
    for (int i = tid; i < 16384; i += 256) sm[OCWP0 + i] = Wp0[i];
    for (int i = tid; i < 256;   i += 256) sm[OCBP0 + i] = bp0[i];
    for (int i = tid; i < 1024;  i += 256) sm[OCWP1 + i] = Wp1[i];
    if (tid < 4) sm[OCBP1 + tid] = bp1[tid];
    __syncthreads();

    const int warp = tid >> 5, lane = tid & 31;
    float* sdec = sm + OCDEC + warp * 64;
    const int tbase = (blockIdx.x * 8 + warp) * CTASKS;
    const size_t scale_stride = (size_t)BB * N_QRY * CIN;

    for (int it = 0; it < CTASKS; it++) {
        int t = tbase + it;
        int b = t >> 14;          // / N_QRY
        int q = t & (N_QRY - 1);

        float w0 = g_w[2 * q], w1 = g_w[2 * q + 1];
        float i0 = w0 / fmaxf(g_cnt[q], 1.f);
        float i1 = w1 / fmaxf(g_cnt[N_QRY + q], 1.f);
        size_t base0 = ((size_t)b * N_QRY + q) * CIN;
        size_t base1 = base0 + scale_stride;

        __syncwarp();
        sdec[lane]      = fmaf(i0, g_acc[base0 + lane],      i1 * g_acc[base1 + lane]);
        sdec[lane + 32] = fmaf(i0, g_acc[base0 + lane + 32], i1 * g_acc[base1 + lane + 32]);
        __syncwarp();

        const int u0 = lane * 8;
        float a[8];
        {
            float4 b0v = ((const float4*)(sm + OCBP0))[lane * 2];
            float4 b1v = ((const float4*)(sm + OCBP0))[lane * 2 + 1];
            a[0] = b0v.x; a[1] = b0v.y; a[2] = b0v.z; a[3] = b0v.w;
            a[4] = b1v.x; a[5] = b1v.y; a[6] = b1v.z; a[7] = b1v.w;
        }
#pragma unroll 1
        for (int k = 0; k < 64; k++) {
            float xk = sdec[k];
            const float4* wrow = (const float4*)(sm + OCWP0 + k * 256 + u0);
            float4 wa = wrow[0], wb = wrow[1];
            a[0] = fmaf(xk, wa.x, a[0]); a[1] = fmaf(xk, wa.y, a[1]);
            a[2] = fmaf(xk, wa.z, a[2]); a[3] = fmaf(xk, wa.w, a[3]);
            a[4] = fmaf(xk, wb.x, a[4]); a[5] = fmaf(xk, wb.y, a[5]);
            a[6] = fmaf(xk, wb.z, a[6]); a[7] = fmaf(xk, wb.w, a[7]);
        }
        float4 o = make_float4(0.f, 0.f, 0.f, 0.f);
#pragma unroll
        for (int j = 0; j < 8; j++) {
            float hg = gelu_f(a[j]);
            float4 wp = ((const float4*)(sm + OCWP1))[u0 + j];
            o.x = fmaf(hg, wp.x, o.x); o.y = fmaf(hg, wp.y, o.y);
            o.z = fmaf(hg, wp.z, o.z); o.w = fmaf(hg, wp.w, o.w);
        }
#pragma unroll
        for (int off = 16; off > 0; off >>= 1) {
            o.x += __shfl_xor_sync(0xffffffffu, o.x, off);
            o.y += __shfl_xor_sync(0xffffffffu, o.y, off);
            o.z += __shfl_xor_sync(0xffffffffu, o.z, off);
            o.w += __shfl_xor_sync(0xffffffffu, o.w, off);
        }
        if (lane == 0) {
            float4 r;
            r.x = o.x + sm[OCBP1 + 0];
            r.y = o.y + sm[OCBP1 + 1];
            r.z = o.z + sm[OCBP1 + 2];
            r.w = o.w + sm[OCBP1 + 3];
            ((float4*)out)[(size_t)b * N_QRY + q] = r;
        }
    }
}

// ---------------- launch ---------------------------------------------------------
extern "C" void kernel_launch(void* const* d_in, const int* in_sizes, int n_in,
                              void* d_out, int out_size)
{
    const float* latc = (const float*)d_in[0];
    const float* rnd  = (const float*)d_in[1];
    const float* qc   = (const float*)d_in[2];
    const int*   src0 = (const int*)d_in[3];
    const int*   qry0 = (const int*)d_in[4];
    const int*   src1 = (const int*)d_in[5];
    const int*   qry1 = (const int*)d_in[6];
    const float* Wk0  = (const float*)d_in[7];
    const float* bk0  = (const float*)d_in[8];
    const float* Wk1  = (const float*)d_in[9];
    const float* bk1  = (const float*)d_in[10];
    const float* Wk2  = (const float*)d_in[11];
    const float* bk2  = (const float*)d_in[12];
    const float* Wsw0 = (const float*)d_in[13];
    const float* bsw0 = (const float*)d_in[14];
    const float* Wsw1 = (const float*)d_in[15];
    const float* bsw1 = (const float*)d_in[16];
    const float* Wp0  = (const float*)d_in[17];
    const float* bp0  = (const float*)d_in[18];
    const float* Wp1  = (const float*)d_in[19];
    const float* bp1  = (const float*)d_in[20];

    const int E0 = in_sizes[3];
    const int E1 = in_sizes[5];

    const size_t smemE = SMEM_EDGE_FLOATS * sizeof(float);
    const size_t smemC = SMEM_COMB_FLOATS * sizeof(float);
    cudaFuncSetAttribute(edge_kernel,    cudaFuncAttributeMaxDynamicSharedMemorySize, (int)smemE);
    cudaFuncSetAttribute(combine_kernel, cudaFuncAttributeMaxDynamicSharedMemorySize, (int)smemC);

    zero_kernel<<<1024, 256>>>();
    switch_kernel<<<(N_QRY + 255) / 256, 256>>>(qc, Wsw0, bsw0, Wsw1, bsw1);
    edge_kernel<<<(E0 + EPB - 1) / EPB, 128, smemE>>>(latc, qc, rnd, src0, qry0,
                                                      Wk0, bk0, Wk1, bk1, Wk2, bk2, 0, E0);
    edge_kernel<<<(E1 + EPB - 1) / EPB, 128, smemE>>>(latc, qc, rnd, src1, qry1,
                                                      Wk0, bk0, Wk1, bk1, Wk2, bk2, 1, E1);
    combine_kernel<<<1024, 256, smemC>>>(Wp0, bp0, Wp1, bp1, (float*)d_out);
}

// round 11
// speedup vs baseline: 1.1265x; 1.1265x over previous
#include <cuda_runtime.h>
#include <cstdint>

#define N_LAT 4096
#define N_QRY 16384
#define BB    4
#define CIN   64

// ---------------- scratch (device globals: allocation-free rule) ----------------
__device__ float g_acc[2 * BB * N_QRY * CIN];   // [scale][b][q][c], 33.5 MB
__device__ float g_cnt[2 * N_QRY];              // edge counts per query per scale
__device__ float g_w[N_QRY * 2];                // softmax switch weights

// ---------------- packed f32x2 helpers (FFMA2 — PTX-only on sm_103a) ------------
__device__ __forceinline__ unsigned long long fma2(unsigned long long a,
                                                   unsigned long long b,
                                                   unsigned long long c) {
    unsigned long long d;
    asm("fma.rn.f32x2 %0, %1, %2, %3;" : "=l"(d) : "l"(a), "l"(b), "l"(c));
    return d;
}
__device__ __forceinline__ unsigned long long dup2(float x) {
    unsigned long long r;
    asm("mov.b64 %0, {%1, %1};" : "=l"(r) : "f"(x));
    return r;
}
__device__ __forceinline__ float2 unpk2(unsigned long long v) {
    float2 r;
    asm("mov.b64 {%0, %1}, %2;" : "=f"(r.x), "=f"(r.y) : "l"(v));
    return r;
}

// ---------------- MUFU-free gelu -------------------------------------------------
// tanh via minimax rational (Eigen coefficients, ~1e-7 abs err for |x| <= 7.905),
// reciprocal via integer-magic seed + 3 FMA Newton steps: ZERO MUFU ops.
__device__ __forceinline__ float ptanh_f(float y) {
    float x = fminf(fmaxf(y, -7.90531110763549805f), 7.90531110763549805f);
    float p = x * x;
    float num = fmaf(p, -2.76076847742355e-16f, 2.00018790482477e-13f);
    num = fmaf(p, num, -8.60467152213735e-11f);
    num = fmaf(p, num, 5.12229709037114e-08f);
    num = fmaf(p, num, 1.48572235717979e-05f);
    num = fmaf(p, num, 6.37261928875436e-04f);
    num = fmaf(p, num, 4.89352455891786e-03f);
    num = num * x;
    float den = fmaf(p, 1.19825839466702e-06f, 1.18534705686654e-04f);
    den = fmaf(p, den, 2.26843463243900e-03f);
    den = fmaf(p, den, 4.89352518554385e-03f);
    // den in [0.00489, ~0.64] > 0: fast reciprocal, 3 Newton refinements
    float r = __uint_as_float(0x7EF311C3u - __float_as_uint(den));
    r = r * fmaf(-den, r, 2.0f);
    r = r * fmaf(-den, r, 2.0f);
    r = r * fmaf(-den, r, 2.0f);
    return num * r;
}
__device__ __forceinline__ float gelu_f(float x) {
    float x2 = x * x;
    float y  = 0.7978845608028654f * x * fmaf(0.044715f, x2, 1.0f);
    return 0.5f * x * (1.0f + ptanh_f(y));
}

// ---------------- kernel 0: zero accumulators -----------------------------------
__global__ void zero_kernel() {
    const size_t n4 = (size_t)(2 * BB * N_QRY * CIN) / 4;
    float4* p = (float4*)g_acc;
    const float4 z = make_float4(0.f, 0.f, 0.f, 0.f);
    for (size_t i = (size_t)blockIdx.x * blockDim.x + threadIdx.x; i < n4;
         i += (size_t)gridDim.x * blockDim.x)
        p[i] = z;
    for (int i = blockIdx.x * blockDim.x + threadIdx.x; i < 2 * N_QRY;
         i += gridDim.x * blockDim.x)
        g_cnt[i] = 0.f;
}

// ---------------- kernel 1: switch MLP + softmax --------------------------------
__global__ void switch_kernel(const float* __restrict__ qc,
                              const float* __restrict__ Wsw0, const float* __restrict__ bsw0,
                              const float* __restrict__ Wsw1, const float* __restrict__ bsw1) {
    int q = blockIdx.x * blockDim.x + threadIdx.x;
    if (q >= N_QRY) return;
    float x0 = qc[2 * q], x1 = qc[2 * q + 1];
    float l0 = bsw1[0], l1 = bsw1[1];
#pragma unroll
    for (int j = 0; j < 16; j++) {
        float hv = bsw0[j];
        hv = fmaf(x0, Wsw0[j], hv);
        hv = fmaf(x1, Wsw0[16 + j], hv);
        hv = fmaxf(hv, 0.f);
        l0 = fmaf(hv, Wsw1[2 * j], l0);
        l1 = fmaf(hv, Wsw1[2 * j + 1], l1);
    }
    float m = fmaxf(l0, l1);
    float e0 = expf(l0 - m), e1 = expf(l1 - m);
    float inv = 1.f / (e0 + e1);
    g_w[2 * q]     = e0 * inv;
    g_w[2 * q + 1] = e1 * inv;
}

// ---------------- kernel 2: per-edge MLP (FFMA2) + segmented reduction -----------
// Phase A: thread = edge. 4->64->64->64 MLP. Activations duplicated into packed
//          f32x2 registers hd[64]; each fma.rn.f32x2 computes TWO output columns
//          using the two 64-bit halves of one LDS.128 weight fetch.
// Phase B: thread = (batch, channel-pair). Register-resident run-length segmented
//          reduction over the block's 128 sorted edges; atomics only at run ends.
#define EPB 128
#define BSTRIDE 66
#define OW0T 0
#define OB0  256
#define OW1  320
#define OB1  4416
#define OW2  4480
#define OB2  8576
#define OIDX 8640
#define OBUF 8896
#define SMEM_EDGE_FLOATS (OBUF + EPB * BSTRIDE)   // 17344 floats = 69376 B

__global__ __launch_bounds__(128, 2) void edge_kernel(
    const float* __restrict__ latc, const float* __restrict__ qc,
    const float* __restrict__ rnd,
    const int* __restrict__ src, const int* __restrict__ qry,
    const float* __restrict__ Wk0, const float* __restrict__ bk0,
    const float* __restrict__ Wk1, const float* __restrict__ bk1,
    const float* __restrict__ Wk2, const float* __restrict__ bk2,
    int scale, int E)
{
    extern __shared__ float sm[];
    const int tid = threadIdx.x;

    // cooperative weight staging (W0 transposed for float4 reads)
    for (int i = tid; i < 256; i += 128) sm[OW0T + (i & 63) * 4 + (i >> 6)] = Wk0[i];
    if (tid < 64) { sm[OB0 + tid] = bk0[tid]; sm[OB1 + tid] = bk1[tid]; sm[OB2 + tid] = bk2[tid]; }
    for (int i = tid; i < 4096; i += 128) { sm[OW1 + i] = Wk1[i]; sm[OW2 + i] = Wk2[i]; }

    const int e = blockIdx.x * EPB + tid;
    int s = 0, q = -1;
    if (e < E) { s = src[e]; q = qry[e]; }
    int* sidx = (int*)(sm + OIDX);
    sidx[tid] = s;
    sidx[EPB + tid] = q;
    float f0 = latc[2 * s], f1 = latc[2 * s + 1];
    float f2 = 0.f, f3 = 0.f;
    if (q >= 0) { f2 = qc[2 * q]; f3 = qc[2 * q + 1]; }
    __syncthreads();

    unsigned long long hd[64];   // packed (h, h) activations
    // layer 1: 4 -> 64 (scalar, tiny), pack gelu result
    {
        const float4* w0 = (const float4*)(sm + OW0T);
#pragma unroll
        for (int j = 0; j < 64; j++) {
            float4 w = w0[j];
            float a = sm[OB0 + j];
            a = fmaf(f0, w.x, a); a = fmaf(f1, w.y, a);
            a = fmaf(f2, w.z, a); a = fmaf(f3, w.w, a);
            hd[j] = dup2(gelu_f(a));
        }
    }
    float* row = sm + OBUF + tid * BSTRIDE;
    // layer 2: 64 -> 64 (gelu), packed FFMA2, write scalars to own SMEM row
    {
        const ulonglong2* Wv = (const ulonglong2*)(sm + OW1);
#pragma unroll 1
        for (int jq = 0; jq < 16; jq++) {
            unsigned long long acc0 = *(const unsigned long long*)(sm + OB1 + 4 * jq);
            unsigned long long acc1 = *(const unsigned long long*)(sm + OB1 + 4 * jq + 2);
#pragma unroll
            for (int k = 0; k < 64; k++) {
                ulonglong2 w = Wv[k * 16 + jq];
                acc0 = fma2(hd[k], w.x, acc0);
                acc1 = fma2(hd[k], w.y, acc1);
            }
            float2 p0 = unpk2(acc0), p1 = unpk2(acc1);
            row[4 * jq + 0] = gelu_f(p0.x); row[4 * jq + 1] = gelu_f(p0.y);
            row[4 * jq + 2] = gelu_f(p1.x); row[4 * jq + 3] = gelu_f(p1.y);
        }
    }
#pragma unroll
    for (int k = 0; k < 64; k++) hd[k] = dup2(row[k]);
    // layer 3: 64 -> 64 (no activation), overwrite row with final k
    {
        const ulonglong2* Wv = (const ulonglong2*)(sm + OW2);
#pragma unroll 1
        for (int jq = 0; jq < 16; jq++) {
            unsigned long long acc0 = *(const unsigned long long*)(sm + OB2 + 4 * jq);
            unsigned long long acc1 = *(const unsigned long long*)(sm + OB2 + 4 * jq + 2);
#pragma unroll
            for (int k = 0; k < 64; k++) {
                ulonglong2 w = Wv[k * 16 + jq];
                acc0 = fma2(hd[k], w.x, acc0);
                acc1 = fma2(hd[k], w.y, acc1);
            }
            float2 p0 = unpk2(acc0), p1 = unpk2(acc1);
            row[4 * jq + 0] = p0.x; row[4 * jq + 1] = p0.y;
            row[4 * jq + 2] = p1.x; row[4 * jq + 3] = p1.y;
        }
    }
    __syncthreads();

    // ---- phase B: segmented reduction over the 128 sorted edges ----
    const int b  = tid >> 5;
    const int c2 = tid & 31;
    const float* rb = rnd + (size_t)b * N_LAT * CIN + 2 * c2;
    float* accBase = g_acc + ((size_t)(scale * BB + b) * N_QRY) * CIN + 2 * c2;
    float* cntBase = g_cnt + scale * N_QRY;

    float ax = 0.f, ay = 0.f;
    int prevq = -1, run = 0;
#pragma unroll 2
    for (int el = 0; el < EPB; el++) {
        int qq = sidx[EPB + el];
        if (qq != prevq) {
            if (prevq >= 0) {
                float* d = accBase + (size_t)prevq * CIN;
                atomicAdd(d, ax);
                atomicAdd(d + 1, ay);
                if (tid == 0) atomicAdd(cntBase + prevq, (float)run);
            }
            ax = 0.f; ay = 0.f; run = 0; prevq = qq;
        }
        if (qq >= 0) {
            int ss = sidx[el];
            float2 kk = *(const float2*)(sm + OBUF + el * BSTRIDE + 2 * c2);
            float2 rr = *(const float2*)(rb + (size_t)ss * CIN);
            ax = fmaf(kk.x, rr.x, ax);
            ay = fmaf(kk.y, rr.y, ay);
            run++;
        }
    }
    if (prevq >= 0) {
        float* d = accBase + (size_t)prevq * CIN;
        atomicAdd(d, ax);
        atomicAdd(d + 1, ay);
        if (tid == 0) atomicAdd(cntBase + prevq, (float)run);
    }
}

// ---------------- kernel 3: combine scales + projection MLP ----------------------
#define OCWP0 0
#define OCBP0 16384
#define OCWP1 16640
#define OCBP1 17664
#define OCDEC 17668
#define SMEM_COMB_FLOATS (OCDEC + 8 * 64)  // 18180 floats = 72720 B
#define CTASKS 8

__global__ __launch_bounds__(256) void combine_kernel(
    const float* __restrict__ Wp0, const float* __restrict__ bp0,
    const float* __restrict__ Wp1, const float* __restrict__ bp1,
    float* __restrict__ out)
{
    extern __shared__ float sm[];
    const int tid = threadIdx.x;
    for (int i = tid; i < 16384; i += 256) sm[OCWP0 + i] = Wp0[i];
    for (int i = tid; i < 256;   i += 256) sm[OCBP0 + i] = bp0[i];
    for (int i = tid; i < 1024;  i += 256) sm[OCWP1 + i] = Wp1[i];
    if (tid < 4) sm[OCBP1 + tid] = bp1[tid];
    __syncthreads();

    const int warp = tid >> 5, lane = tid & 31;
    float* sdec = sm + OCDEC + warp * 64;
    const int tbase = (blockIdx.x * 8 + warp) * CTASKS;
    const size_t scale_stride = (size_t)BB * N_QRY * CIN;

    for (int it = 0; it < CTASKS; it++) {
        int t = tbase + it;
        int b = t >> 14;          // / N_QRY
        int q = t & (N_QRY - 1);

        float w0 = g_w[2 * q], w1 = g_w[2 * q + 1];
        float i0 = w0 / fmaxf(g_cnt[q], 1.f);
        float i1 = w1 / fmaxf(g_cnt[N_QRY + q], 1.f);
        size_t base0 = ((size_t)b * N_QRY + q) * CIN;
        size_t base1 = base0 + scale_stride;

        __syncwarp();
        sdec[lane]      = fmaf(i0, g_acc[base0 + lane],      i1 * g_acc[base1 + lane]);
        sdec[lane + 32] = fmaf(i0, g_acc[base0 + lane + 32], i1 * g_acc[base1 + lane + 32]);
        __syncwarp();

        const int u0 = lane * 8;
        float a[8];
        {
            float4 b0v = ((const float4*)(sm + OCBP0))[lane * 2];
            float4 b1v = ((const float4*)(sm + OCBP0))[lane * 2 + 1];
            a[0] = b0v.x; a[1] = b0v.y; a[2] = b0v.z; a[3] = b0v.w;
            a[4] = b1v.x; a[5] = b1v.y; a[6] = b1v.z; a[7] = b1v.w;
        }
#pragma unroll 1
        for (int k = 0; k < 64; k++) {
            float xk = sdec[k];
            const float4* wrow = (const float4*)(sm + OCWP0 + k * 256 + u0);
            float4 wa = wrow[0], wb = wrow[1];
            a[0] = fmaf(xk, wa.x, a[0]); a[1] = fmaf(xk, wa.y, a[1]);
            a[2] = fmaf(xk, wa.z, a[2]); a[3] = fmaf(xk, wa.w, a[3]);
            a[4] = fmaf(xk, wb.x, a[4]); a[5] = fmaf(xk, wb.y, a[5]);
            a[6] = fmaf(xk, wb.z, a[6]); a[7] = fmaf(xk, wb.w, a[7]);
        }
        float4 o = make_float4(0.f, 0.f, 0.f, 0.f);
#pragma unroll
        for (int j = 0; j < 8; j++) {
            float hg = gelu_f(a[j]);
            float4 wp = ((const float4*)(sm + OCWP1))[u0 + j];
            o.x = fmaf(hg, wp.x, o.x); o.y = fmaf(hg, wp.y, o.y);
            o.z = fmaf(hg, wp.z, o.z); o.w = fmaf(hg, wp.w, o.w);
        }
#pragma unroll
        for (int off = 16; off > 0; off >>= 1) {
            o.x += __shfl_xor_sync(0xffffffffu, o.x, off);
            o.y += __shfl_xor_sync(0xffffffffu, o.y, off);
            o.z += __shfl_xor_sync(0xffffffffu, o.z, off);
            o.w += __shfl_xor_sync(0xffffffffu, o.w, off);
        }
        if (lane == 0) {
            float4 r;
            r.x = o.x + sm[OCBP1 + 0];
            r.y = o.y + sm[OCBP1 + 1];
            r.z = o.z + sm[OCBP1 + 2];
            r.w = o.w + sm[OCBP1 + 3];
            ((float4*)out)[(size_t)b * N_QRY + q] = r;
        }
    }
}

// ---------------- launch ---------------------------------------------------------
extern "C" void kernel_launch(void* const* d_in, const int* in_sizes, int n_in,
                              void* d_out, int out_size)
{
    const float* latc = (const float*)d_in[0];
    const float* rnd  = (const float*)d_in[1];
    const float* qc   = (const float*)d_in[2];
    const int*   src0 = (const int*)d_in[3];
    const int*   qry0 = (const int*)d_in[4];
    const int*   src1 = (const int*)d_in[5];
    const int*   qry1 = (const int*)d_in[6];
    const float* Wk0  = (const float*)d_in[7];
    const float* bk0  = (const float*)d_in[8];
    const float* Wk1  = (const float*)d_in[9];
    const float* bk1  = (const float*)d_in[10];
    const float* Wk2  = (const float*)d_in[11];
    const float* bk2  = (const float*)d_in[12];
    const float* Wsw0 = (const float*)d_in[13];
    const float* bsw0 = (const float*)d_in[14];
    const float* Wsw1 = (const float*)d_in[15];
    const float* bsw1 = (const float*)d_in[16];
    const float* Wp0  = (const float*)d_in[17];
    const float* bp0  = (const float*)d_in[18];
    const float* Wp1  = (const float*)d_in[19];
    const float* bp1  = (const float*)d_in[20];

    const int E0 = in_sizes[3];
    const int E1 = in_sizes[5];

    const size_t smemE = SMEM_EDGE_FLOATS * sizeof(float);
    const size_t smemC = SMEM_COMB_FLOATS * sizeof(float);
    cudaFuncSetAttribute(edge_kernel,    cudaFuncAttributeMaxDynamicSharedMemorySize, (int)smemE);
    cudaFuncSetAttribute(combine_kernel, cudaFuncAttributeMaxDynamicSharedMemorySize, (int)smemC);

    zero_kernel<<<1024, 256>>>();
    switch_kernel<<<(N_QRY + 255) / 256, 256>>>(qc, Wsw0, bsw0, Wsw1, bsw1);
    edge_kernel<<<(E0 + EPB - 1) / EPB, 128, smemE>>>(latc, qc, rnd, src0, qry0,
                                                      Wk0, bk0, Wk1, bk1, Wk2, bk2, 0, E0);
    edge_kernel<<<(E1 + EPB - 1) / EPB, 128, smemE>>>(latc, qc, rnd, src1, qry1,
                                                      Wk0, bk0, Wk1, bk1, Wk2, bk2, 1, E1);
    combine_kernel<<<1024, 256, smemC>>>(Wp0, bp0, Wp1, bp1, (float*)d_out);
}

// round 12
// speedup vs baseline: 1.3244x; 1.1757x over previous
#include <cuda_runtime.h>
#include <cuda_bf16.h>
#include <cstdint>

#define N_LAT 4096
#define N_QRY 16384
#define BB    4
#define CIN   64

// ---------------- scratch (device globals: allocation-free rule) ----------------
__device__ float g_acc[2 * BB * N_QRY * CIN];   // [scale][b][q][c], 33.5 MB
__device__ float g_cnt[2 * N_QRY];              // edge counts per query per scale
__device__ float g_w[N_QRY * 2];                // softmax switch weights

// ---------------- helpers --------------------------------------------------------
__device__ __forceinline__ uint32_t pkbf(float a, float b) {
    __nv_bfloat162 t = __floats2bfloat162_rn(a, b);
    return *reinterpret_cast<uint32_t*>(&t);
}
__device__ __forceinline__ float gelu_f(float x) {
    float x2 = x * x;
    float y  = 0.7978845608028654f * x * fmaf(0.044715f, x2, 1.0f);
    float e  = __expf(2.0f * y);
    float t  = 1.0f - __fdividef(2.0f, e + 1.0f); // == tanh(y)
    return 0.5f * x * (1.0f + t);
}
__device__ __forceinline__ uint32_t smem_u32(const void* p) {
    uint32_t a;
    asm("{ .reg .u64 t; cvta.to.shared.u64 t, %1; cvt.u32.u64 %0, t; }" : "=r"(a) : "l"(p));
    return a;
}
__device__ __forceinline__ void ldmx4(uint32_t& r0, uint32_t& r1, uint32_t& r2, uint32_t& r3,
                                      uint32_t addr) {
    asm volatile("ldmatrix.sync.aligned.m8n8.x4.shared.b16 {%0,%1,%2,%3}, [%4];"
                 : "=r"(r0), "=r"(r1), "=r"(r2), "=r"(r3) : "r"(addr));
}
#define MMA16816(c, a0, a1, a2, a3, b0, b1)                                   \
    asm volatile("mma.sync.aligned.m16n8k16.row.col.f32.bf16.bf16.f32 "       \
                 "{%0,%1,%2,%3}, {%4,%5,%6,%7}, {%8,%9}, {%0,%1,%2,%3};"      \
                 : "+f"((c)[0]), "+f"((c)[1]), "+f"((c)[2]), "+f"((c)[3])     \
                 : "r"(a0), "r"(a1), "r"(a2), "r"(a3), "r"(b0), "r"(b1))

// ---------------- kernel 0: zero accumulators -----------------------------------
__global__ void zero_kernel() {
    const size_t n4 = (size_t)(2 * BB * N_QRY * CIN) / 4;
    float4* p = (float4*)g_acc;
    const float4 z = make_float4(0.f, 0.f, 0.f, 0.f);
    for (size_t i = (size_t)blockIdx.x * blockDim.x + threadIdx.x; i < n4;
         i += (size_t)gridDim.x * blockDim.x)
        p[i] = z;
    for (int i = blockIdx.x * blockDim.x + threadIdx.x; i < 2 * N_QRY;
         i += gridDim.x * blockDim.x)
        g_cnt[i] = 0.f;
}

// ---------------- kernel 1: switch MLP + softmax --------------------------------
__global__ void switch_kernel(const float* __restrict__ qc,
                              const float* __restrict__ Wsw0, const float* __restrict__ bsw0,
                              const float* __restrict__ Wsw1, const float* __restrict__ bsw1) {
    int q = blockIdx.x * blockDim.x + threadIdx.x;
    if (q >= N_QRY) return;
    float x0 = qc[2 * q], x1 = qc[2 * q + 1];
    float l0 = bsw1[0], l1 = bsw1[1];
#pragma unroll
    for (int j = 0; j < 16; j++) {
        float hv = bsw0[j];
        hv = fmaf(x0, Wsw0[j], hv);
        hv = fmaf(x1, Wsw0[16 + j], hv);
        hv = fmaxf(hv, 0.f);
        l0 = fmaf(hv, Wsw1[2 * j], l0);
        l1 = fmaf(hv, Wsw1[2 * j + 1], l1);
    }
    float m = fmaxf(l0, l1);
    float e0 = expf(l0 - m), e1 = expf(l1 - m);
    float inv = 1.f / (e0 + e1);
    g_w[2 * q]     = e0 * inv;
    g_w[2 * q + 1] = e1 * inv;
}

// ---------------- kernel 2: HMMA edge MLP + segmented reduction ------------------
// Layers 2/3: warp-level mma.sync bf16 GEMMs with 3-term hi/lo split (fp32-grade).
// Each warp owns 32 edge-rows: layer1 per-thread -> SW128 A tiles -> ldmatrix/mma
// -> gelu in fragments -> re-split -> mma -> fp32 k buffer -> phase B (unchanged).
#define EPB 128
// byte offsets in dynamic SMEM (tile bases 128B-aligned)
#define X_IDX  0        // src[128] @0, qry[128] @512
#define X_W0T  1024     // 256 floats, W0 transposed
#define X_B0   2048     // 64 floats
#define X_B1   2304
#define X_B2   2560     // ends 2816
#define X_W2H  2816     // 64 x 128B bf16 (SW128)
#define X_W2L  11008
#define X_AH   19200    // 128 x 128B bf16 (SW128)
#define X_AL   35584
#define X_W1H  51968
#define X_W1L  60160    // ends 68352
#define X_K    19200    // fp32 k buffer overlay (A/W1 dead), 128 rows x 264B
#define SMEM_EDGE_BYTES 68352

// one GEMM layer: acc[2][8][4] += split-bf16( A[32wid..+31, 0:64] @ W[0:64]^T )
__device__ __forceinline__ void mma_layer(uint32_t sbAH, uint32_t sbAL,
                                          uint32_t sbWH, uint32_t sbWL,
                                          int wid, int lane, float acc[2][8][4]) {
    const int r7   = lane & 7;
    const int arow = r7 + (((lane >> 3) & 1) << 3);   // A: i&1 -> +8 rows
    const int asel = lane >> 4;                       // A: i>>1 -> +1 chunk
    const int brow = r7 + ((lane >> 4) << 3);         // B: i>>1 -> +8 rows
    const int bsel = (lane >> 3) & 1;                 // B: i&1  -> +1 chunk
#pragma unroll
    for (int ks = 0; ks < 4; ks++) {
        uint32_t ah[2][4], al[2][4];
#pragma unroll
        for (int mi = 0; mi < 2; mi++) {
            uint32_t off = (uint32_t)((32 * wid + mi * 16 + arow) * 128 +
                                      (((ks * 2 + asel) ^ r7) << 4));
            ldmx4(ah[mi][0], ah[mi][1], ah[mi][2], ah[mi][3], sbAH + off);
            ldmx4(al[mi][0], al[mi][1], al[mi][2], al[mi][3], sbAL + off);
        }
#pragma unroll
        for (int p = 0; p < 4; p++) {
            uint32_t woff = (uint32_t)((p * 16 + brow) * 128 +
                                       (((ks * 2 + bsel) ^ r7) << 4));
            uint32_t bh0, bh1, bh2, bh3, bl0, bl1, bl2, bl3;
            ldmx4(bh0, bh1, bh2, bh3, sbWH + woff);
            ldmx4(bl0, bl1, bl2, bl3, sbWL + woff);
#pragma unroll
            for (int mi = 0; mi < 2; mi++) {
                MMA16816(acc[mi][2 * p],     ah[mi][0], ah[mi][1], ah[mi][2], ah[mi][3], bh0, bh1);
                MMA16816(acc[mi][2 * p],     al[mi][0], al[mi][1], al[mi][2], al[mi][3], bh0, bh1);
                MMA16816(acc[mi][2 * p],     ah[mi][0], ah[mi][1], ah[mi][2], ah[mi][3], bl0, bl1);
                MMA16816(acc[mi][2 * p + 1], ah[mi][0], ah[mi][1], ah[mi][2], ah[mi][3], bh2, bh3);
                MMA16816(acc[mi][2 * p + 1], al[mi][0], al[mi][1], al[mi][2], al[mi][3], bh2, bh3);
                MMA16816(acc[mi][2 * p + 1], ah[mi][0], ah[mi][1], ah[mi][2], ah[mi][3], bl2, bl3);
            }
        }
    }
}

__global__ __launch_bounds__(128, 3) void edge_kernel(
    const float* __restrict__ latc, const float* __restrict__ qc,
    const float* __restrict__ rnd,
    const int* __restrict__ src, const int* __restrict__ qry,
    const float* __restrict__ Wk0, const float* __restrict__ bk0,
    const float* __restrict__ Wk1, const float* __restrict__ bk1,
    const float* __restrict__ Wk2, const float* __restrict__ bk2,
    int scale, int E)
{
    extern __shared__ char smc[];
    float* smf = (float*)smc;
    const uint32_t sb = smem_u32(smc);
    const int tid = threadIdx.x, wid = tid >> 5, lane = tid & 31;

    // ---- stage weights: transpose to [j][k], bf16 hi/lo, SW128 swizzle ----
    for (int i = tid; i < 4096; i += 128) {
        int j = i & 63, k = i >> 6;
        uint32_t off = (uint32_t)(j * 128 + (((k >> 3) ^ (j & 7)) << 4) + (k & 7) * 2);
        float w1 = Wk1[i];
        __nv_bfloat16 h1 = __float2bfloat16_rn(w1);
        *(__nv_bfloat16*)(smc + X_W1H + off) = h1;
        *(__nv_bfloat16*)(smc + X_W1L + off) = __float2bfloat16_rn(w1 - __bfloat162float(h1));
        float w2 = Wk2[i];
        __nv_bfloat16 h2 = __float2bfloat16_rn(w2);
        *(__nv_bfloat16*)(smc + X_W2H + off) = h2;
        *(__nv_bfloat16*)(smc + X_W2L + off) = __float2bfloat16_rn(w2 - __bfloat162float(h2));
    }
    for (int i = tid; i < 256; i += 128) smf[(X_W0T >> 2) + (i & 63) * 4 + (i >> 6)] = Wk0[i];
    if (tid < 64) {
        smf[(X_B0 >> 2) + tid] = bk0[tid];
        smf[(X_B1 >> 2) + tid] = bk1[tid];
        smf[(X_B2 >> 2) + tid] = bk2[tid];
    }

    const int e = blockIdx.x * EPB + tid;
    int s = 0, q = -1;
    if (e < E) { s = src[e]; q = qry[e]; }
    int* sidx = (int*)(smc + X_IDX);
    sidx[tid] = s;
    sidx[EPB + tid] = q;
    float f0 = latc[2 * s], f1 = latc[2 * s + 1];
    float f2 = 0.f, f3 = 0.f;
    if (q >= 0) { f2 = qc[2 * q]; f3 = qc[2 * q + 1]; }
    __syncthreads();

    // ---- layer 1: 4 -> 64 per-thread, gelu, hi/lo split -> A tiles (own row) ----
    {
        const float4* w0 = (const float4*)(smc + X_W0T);
        const float* b0 = smf + (X_B0 >> 2);
#pragma unroll
        for (int c = 0; c < 8; c++) {
            float v[8];
#pragma unroll
            for (int jj = 0; jj < 8; jj++) {
                int j = c * 8 + jj;
                float4 w = w0[j];
                float a = b0[j];
                a = fmaf(f0, w.x, a); a = fmaf(f1, w.y, a);
                a = fmaf(f2, w.z, a); a = fmaf(f3, w.w, a);
                v[jj] = gelu_f(a);
            }
            uint32_t h[4], l[4];
#pragma unroll
            for (int m = 0; m < 4; m++) {
                h[m] = pkbf(v[2 * m], v[2 * m + 1]);
                float fx = __uint_as_float(h[m] << 16);
                float fy = __uint_as_float(h[m] & 0xFFFF0000u);
                l[m] = pkbf(v[2 * m] - fx, v[2 * m + 1] - fy);
            }
            uint32_t off = (uint32_t)(tid * 128 + ((c ^ (tid & 7)) << 4));
            *(uint4*)(smc + X_AH + off) = make_uint4(h[0], h[1], h[2], h[3]);
            *(uint4*)(smc + X_AL + off) = make_uint4(l[0], l[1], l[2], l[3]);
        }
    }
    __syncwarp();

    // ---- layer 2: MMA, then gelu + re-split in fragments (warp-own rows) ----
    float acc[2][8][4];
#pragma unroll
    for (int mi = 0; mi < 2; mi++)
#pragma unroll
        for (int ni = 0; ni < 8; ni++)
#pragma unroll
            for (int z = 0; z < 4; z++) acc[mi][ni][z] = 0.f;

    mma_layer(sb + X_AH, sb + X_AL, sb + X_W1H, sb + X_W1L, wid, lane, acc);

    {
        const float* b1 = smf + (X_B1 >> 2);
        const int g = lane >> 2, t = lane & 3;
#pragma unroll
        for (int mi = 0; mi < 2; mi++) {
            int row0 = 32 * wid + mi * 16 + g;
#pragma unroll
            for (int ni = 0; ni < 8; ni++) {
                float2 bb = *(const float2*)(b1 + ni * 8 + t * 2);
                float v0 = gelu_f(acc[mi][ni][0] + bb.x);
                float v1 = gelu_f(acc[mi][ni][1] + bb.y);
                float v2 = gelu_f(acc[mi][ni][2] + bb.x);
                float v3 = gelu_f(acc[mi][ni][3] + bb.y);
                uint32_t h0 = pkbf(v0, v1);
                uint32_t l0 = pkbf(v0 - __uint_as_float(h0 << 16),
                                   v1 - __uint_as_float(h0 & 0xFFFF0000u));
                uint32_t h1 = pkbf(v2, v3);
                uint32_t l1 = pkbf(v2 - __uint_as_float(h1 << 16),
                                   v3 - __uint_as_float(h1 & 0xFFFF0000u));
                int r1 = row0 + 8;
                uint32_t offA = (uint32_t)(row0 * 128 + ((ni ^ (row0 & 7)) << 4) + t * 4);
                uint32_t offB = (uint32_t)(r1 * 128 + ((ni ^ (r1 & 7)) << 4) + t * 4);
                *(uint32_t*)(smc + X_AH + offA) = h0;
                *(uint32_t*)(smc + X_AL + offA) = l0;
                *(uint32_t*)(smc + X_AH + offB) = h1;
                *(uint32_t*)(smc + X_AL + offB) = l1;
                acc[mi][ni][0] = 0.f; acc[mi][ni][1] = 0.f;
                acc[mi][ni][2] = 0.f; acc[mi][ni][3] = 0.f;
            }
        }
    }
    __syncwarp();

    // ---- layer 3: MMA (no activation) ----
    mma_layer(sb + X_AH, sb + X_AL, sb + X_W2H, sb + X_W2L, wid, lane, acc);
    __syncthreads();   // A/W1 region now dead everywhere; k buffer overlays it

    {
        const float* b2 = smf + (X_B2 >> 2);
        const int g = lane >> 2, t = lane & 3;
#pragma unroll
        for (int mi = 0; mi < 2; mi++) {
            int row0 = 32 * wid + mi * 16 + g;
#pragma unroll
            for (int ni = 0; ni < 8; ni++) {
                float2 bb = *(const float2*)(b2 + ni * 8 + t * 2);
                int colb = (ni * 8 + t * 2) * 4;
                *(float2*)(smc + X_K + row0 * 264 + colb) =
                    make_float2(acc[mi][ni][0] + bb.x, acc[mi][ni][1] + bb.y);
                *(float2*)(smc + X_K + (row0 + 8) * 264 + colb) =
                    make_float2(acc[mi][ni][2] + bb.x, acc[mi][ni][3] + bb.y);
            }
        }
    }
    __syncthreads();

    // ---- phase B: segmented reduction over the 128 sorted edges ----
    const int b  = wid;
    const int c2 = lane;
    const float* rb = rnd + (size_t)b * N_LAT * CIN + 2 * c2;
    float* accBase = g_acc + ((size_t)(scale * BB + b) * N_QRY) * CIN + 2 * c2;
    float* cntBase = g_cnt + scale * N_QRY;

    float ax = 0.f, ay = 0.f;
    int prevq = -1, run = 0;
#pragma unroll 2
    for (int el = 0; el < EPB; el++) {
        int qq = sidx[EPB + el];
        if (qq != prevq) {
            if (prevq >= 0) {
                float* d = accBase + (size_t)prevq * CIN;
                atomicAdd(d, ax);
                atomicAdd(d + 1, ay);
                if (tid == 0) atomicAdd(cntBase + prevq, (float)run);
            }
            ax = 0.f; ay = 0.f; run = 0; prevq = qq;
        }
        if (qq >= 0) {
            int ss = sidx[el];
            float2 kk = *(const float2*)(smc + X_K + el * 264 + c2 * 8);
            float2 rr = *(const float2*)(rb + (size_t)ss * CIN);
            ax = fmaf(kk.x, rr.x, ax);
            ay = fmaf(kk.y, rr.y, ay);
            run++;
        }
    }
    if (prevq >= 0) {
        float* d = accBase + (size_t)prevq * CIN;
        atomicAdd(d, ax);
        atomicAdd(d + 1, ay);
        if (tid == 0) atomicAdd(cntBase + prevq, (float)run);
    }
}

// ---------------- kernel 3: combine scales + projection MLP ----------------------
#define OCWP0 0
#define OCBP0 16384
#define OCWP1 16640
#define OCBP1 17664
#define OCDEC 17668
#define SMEM_COMB_FLOATS (OCDEC + 8 * 64)  // 18180 floats = 72720 B
#define CTASKS 8

__global__ __launch_bounds__(256) void combine_kernel(
    const float* __restrict__ Wp0, const float* __restrict__ bp0,
    const float* __restrict__ Wp1, const float* __restrict__ bp1,
    float* __restrict__ out)
{
    extern __shared__ float sm[];
    const int tid = threadIdx.x;
    for (int i = tid; i < 16384; i += 256) sm[OCWP0 + i] = Wp0[i];
    for (int i = tid; i < 256;   i += 256) sm[OCBP0 + i] = bp0[i];
    for (int i = tid; i < 1024;  i += 256) sm[OCWP1 + i] = Wp1[i];
    if (tid < 4) sm[OCBP1 + tid] = bp1[tid];
    __syncthreads();

    const int warp = tid >> 5, lane = tid & 31;
    float* sdec = sm + OCDEC + warp * 64;
    const int tbase = (blockIdx.x * 8 + warp) * CTASKS;
    const size_t scale_stride = (size_t)BB * N_QRY * CIN;

    for (int it = 0; it < CTASKS; it++) {
        int t = tbase + it;
        int b = t >> 14;          // / N_QRY
        int q = t & (N_QRY - 1);

        float w0 = g_w[2 * q], w1 = g_w[2 * q + 1];
        float i0 = w0 / fmaxf(g_cnt[q], 1.f);
        float i1 = w1 / fmaxf(g_cnt[N_QRY + q], 1.f);
        size_t base0 = ((size_t)b * N_QRY + q) * CIN;
        size_t base1 = base0 + scale_stride;

        __syncwarp();
        sdec[lane]      = fmaf(i0, g_acc[base0 + lane],      i1 * g_acc[base1 + lane]);
        sdec[lane + 32] = fmaf(i0, g_acc[base0 + lane + 32], i1 * g_acc[base1 + lane + 32]);
        __syncwarp();

        const int u0 = lane * 8;
        float a[8];
        {
            float4 b0v = ((const float4*)(sm + OCBP0))[lane * 2];
            float4 b1v = ((const float4*)(sm + OCBP0))[lane * 2 + 1];
            a[0] = b0v.x; a[1] = b0v.y; a[2] = b0v.z; a[3] = b0v.w;
            a[4] = b1v.x; a[5] = b1v.y; a[6] = b1v.z; a[7] = b1v.w;
        }
#pragma unroll 1
        for (int k = 0; k < 64; k++) {
            float xk = sdec[k];
            const float4* wrow = (const float4*)(sm + OCWP0 + k * 256 + u0);
            float4 wa = wrow[0], wb = wrow[1];
            a[0] = fmaf(xk, wa.x, a[0]); a[1] = fmaf(xk, wa.y, a[1]);
            a[2] = fmaf(xk, wa.z, a[2]); a[3] = fmaf(xk, wa.w, a[3]);
            a[4] = fmaf(xk, wb.x, a[4]); a[5] = fmaf(xk, wb.y, a[5]);
            a[6] = fmaf(xk, wb.z, a[6]); a[7] = fmaf(xk, wb.w, a[7]);
        }
        float4 o = make_float4(0.f, 0.f, 0.f, 0.f);
#pragma unroll
        for (int j = 0; j < 8; j++) {
            float hg = gelu_f(a[j]);
            float4 wp = ((const float4*)(sm + OCWP1))[u0 + j];
            o.x = fmaf(hg, wp.x, o.x); o.y = fmaf(hg, wp.y, o.y);
            o.z = fmaf(hg, wp.z, o.z); o.w = fmaf(hg, wp.w, o.w);
        }
#pragma unroll
        for (int off = 16; off > 0; off >>= 1) {
            o.x += __shfl_xor_sync(0xffffffffu, o.x, off);
            o.y += __shfl_xor_sync(0xffffffffu, o.y, off);
            o.z += __shfl_xor_sync(0xffffffffu, o.z, off);
            o.w += __shfl_xor_sync(0xffffffffu, o.w, off);
        }
        if (lane == 0) {
            float4 r;
            r.x = o.x + sm[OCBP1 + 0];
            r.y = o.y + sm[OCBP1 + 1];
            r.z = o.z + sm[OCBP1 + 2];
            r.w = o.w + sm[OCBP1 + 3];
            ((float4*)out)[(size_t)b * N_QRY + q] = r;
        }
    }
}

// ---------------- launch ---------------------------------------------------------
extern "C" void kernel_launch(void* const* d_in, const int* in_sizes, int n_in,
                              void* d_out, int out_size)
{
    const float* latc = (const float*)d_in[0];
    const float* rnd  = (const float*)d_in[1];
    const float* qc   = (const float*)d_in[2];
    const int*   src0 = (const int*)d_in[3];
    const int*   qry0 = (const int*)d_in[4];
    const int*   src1 = (const int*)d_in[5];
    const int*   qry1 = (const int*)d_in[6];
    const float* Wk0  = (const float*)d_in[7];
    const float* bk0  = (const float*)d_in[8];
    const float* Wk1  = (const float*)d_in[9];
    const float* bk1  = (const float*)d_in[10];
    const float* Wk2  = (const float*)d_in[11];
    const float* bk2  = (const float*)d_in[12];
    const float* Wsw0 = (const float*)d_in[13];
    const float* bsw0 = (const float*)d_in[14];
    const float* Wsw1 = (const float*)d_in[15];
    const float* bsw1 = (const float*)d_in[16];
    const float* Wp0  = (const float*)d_in[17];
    const float* bp0  = (const float*)d_in[18];
    const float* Wp1  = (const float*)d_in[19];
    const float* bp1  = (const float*)d_in[20];

    const int E0 = in_sizes[3];
    const int E1 = in_sizes[5];

    const size_t smemC = SMEM_COMB_FLOATS * sizeof(float);
    cudaFuncSetAttribute(edge_kernel,    cudaFuncAttributeMaxDynamicSharedMemorySize, SMEM_EDGE_BYTES);
    cudaFuncSetAttribute(combine_kernel, cudaFuncAttributeMaxDynamicSharedMemorySize, (int)smemC);

    zero_kernel<<<1024, 256>>>();
    switch_kernel<<<(N_QRY + 255) / 256, 256>>>(qc, Wsw0, bsw0, Wsw1, bsw1);
    edge_kernel<<<(E0 + EPB - 1) / EPB, 128, SMEM_EDGE_BYTES>>>(latc, qc, rnd, src0, qry0,
                                                                Wk0, bk0, Wk1, bk1, Wk2, bk2, 0, E0);
    edge_kernel<<<(E1 + EPB - 1) / EPB, 128, SMEM_EDGE_BYTES>>>(latc, qc, rnd, src1, qry1,
                                                                Wk0, bk0, Wk1, bk1, Wk2, bk2, 1, E1);
    combine_kernel<<<1024, 256, smemC>>>(Wp0, bp0, Wp1, bp1, (float*)d_out);
}

// round 13
// speedup vs baseline: 2.0762x; 1.5676x over previous
#include <cuda_runtime.h>
#include <cuda_bf16.h>
#include <cstdint>

#define N_LAT 4096
#define N_QRY 16384
#define BB    4
#define CIN   64

// ---------------- scratch (device globals: allocation-free rule) ----------------
__device__ float g_acc[2 * BB * N_QRY * CIN];   // [scale][b][q][c], 33.5 MB
__device__ float g_cnt[2 * N_QRY];              // edge counts per query per scale
__device__ float g_w[N_QRY * 2];                // softmax switch weights
__device__ unsigned char g_wt[32768];           // prepped W1H|W1L|W2H|W2L swizzled tiles

// ---------------- helpers --------------------------------------------------------
__device__ __forceinline__ unsigned long long fma2(unsigned long long a,
                                                   unsigned long long b,
                                                   unsigned long long c) {
    unsigned long long d;
    asm("fma.rn.f32x2 %0, %1, %2, %3;" : "=l"(d) : "l"(a), "l"(b), "l"(c));
    return d;
}
__device__ __forceinline__ unsigned long long dup2(float x) {
    unsigned long long r;
    asm("mov.b64 %0, {%1, %1};" : "=l"(r) : "f"(x));
    return r;
}
__device__ __forceinline__ float2 unpk2(unsigned long long v) {
    float2 r;
    asm("mov.b64 {%0, %1}, %2;" : "=f"(r.x), "=f"(r.y) : "l"(v));
    return r;
}
__device__ __forceinline__ uint32_t pkbf(float a, float b) {
    __nv_bfloat162 t = __floats2bfloat162_rn(a, b);
    return *reinterpret_cast<uint32_t*>(&t);
}
__device__ __forceinline__ float gelu_f(float x) {
    float x2 = x * x;
    float y  = 0.7978845608028654f * x * fmaf(0.044715f, x2, 1.0f);
    float e  = __expf(2.0f * y);
    float t  = 1.0f - __fdividef(2.0f, e + 1.0f); // == tanh(y)
    return 0.5f * x * (1.0f + t);
}
__device__ __forceinline__ uint32_t smem_u32(const void* p) {
    uint32_t a;
    asm("{ .reg .u64 t; cvta.to.shared.u64 t, %1; cvt.u32.u64 %0, t; }" : "=r"(a) : "l"(p));
    return a;
}
__device__ __forceinline__ void ldmx4(uint32_t& r0, uint32_t& r1, uint32_t& r2, uint32_t& r3,
                                      uint32_t addr) {
    asm volatile("ldmatrix.sync.aligned.m8n8.x4.shared.b16 {%0,%1,%2,%3}, [%4];"
                 : "=r"(r0), "=r"(r1), "=r"(r2), "=r"(r3) : "r"(addr));
}
#define MMA16816(c, a0, a1, a2, a3, b0, b1)                                   \
    asm volatile("mma.sync.aligned.m16n8k16.row.col.f32.bf16.bf16.f32 "       \
                 "{%0,%1,%2,%3}, {%4,%5,%6,%7}, {%8,%9}, {%0,%1,%2,%3};"      \
                 : "+f"((c)[0]), "+f"((c)[1]), "+f"((c)[2]), "+f"((c)[3])     \
                 : "r"(a0), "r"(a1), "r"(a2), "r"(a3), "r"(b0), "r"(b1))

// ---------------- kernel 0: zero accumulators -----------------------------------
__global__ void zero_kernel() {
    const size_t n4 = (size_t)(2 * BB * N_QRY * CIN) / 4;
    float4* p = (float4*)g_acc;
    const float4 z = make_float4(0.f, 0.f, 0.f, 0.f);
    for (size_t i = (size_t)blockIdx.x * blockDim.x + threadIdx.x; i < n4;
         i += (size_t)gridDim.x * blockDim.x)
        p[i] = z;
    for (int i = blockIdx.x * blockDim.x + threadIdx.x; i < 2 * N_QRY;
         i += gridDim.x * blockDim.x)
        g_cnt[i] = 0.f;
}

// ---------------- prep kernel: build swizzled bf16 hi/lo weight tiles ------------
__global__ void prep_kernel(const float* __restrict__ Wk1, const float* __restrict__ Wk2) {
    int i = blockIdx.x * blockDim.x + threadIdx.x;   // 0..4095 over [k][j]
    if (i >= 4096) return;
    int j = i & 63, k = i >> 6;
    uint32_t off = (uint32_t)(j * 128 + (((k >> 3) ^ (j & 7)) << 4) + (k & 7) * 2);
    float w1 = Wk1[i];
    __nv_bfloat16 h1 = __float2bfloat16_rn(w1);
    *(__nv_bfloat16*)(g_wt + 0     + off) = h1;
    *(__nv_bfloat16*)(g_wt + 8192  + off) = __float2bfloat16_rn(w1 - __bfloat162float(h1));
    float w2 = Wk2[i];
    __nv_bfloat16 h2 = __float2bfloat16_rn(w2);
    *(__nv_bfloat16*)(g_wt + 16384 + off) = h2;
    *(__nv_bfloat16*)(g_wt + 24576 + off) = __float2bfloat16_rn(w2 - __bfloat162float(h2));
}

// ---------------- kernel 1: switch MLP + softmax --------------------------------
__global__ void switch_kernel(const float* __restrict__ qc,
                              const float* __restrict__ Wsw0, const float* __restrict__ bsw0,
                              const float* __restrict__ Wsw1, const float* __restrict__ bsw1) {
    int q = blockIdx.x * blockDim.x + threadIdx.x;
    if (q >= N_QRY) return;
    float x0 = qc[2 * q], x1 = qc[2 * q + 1];
    float l0 = bsw1[0], l1 = bsw1[1];
#pragma unroll
    for (int j = 0; j < 16; j++) {
        float hv = bsw0[j];
        hv = fmaf(x0, Wsw0[j], hv);
        hv = fmaf(x1, Wsw0[16 + j], hv);
        hv = fmaxf(hv, 0.f);
        l0 = fmaf(hv, Wsw1[2 * j], l0);
        l1 = fmaf(hv, Wsw1[2 * j + 1], l1);
    }
    float m = fmaxf(l0, l1);
    float e0 = expf(l0 - m), e1 = expf(l1 - m);
    float inv = 1.f / (e0 + e1);
    g_w[2 * q]     = e0 * inv;
    g_w[2 * q + 1] = e1 * inv;
}

// ---------------- kernel 2: HMMA edge MLP + segmented reduction ------------------
#define EPB 128
// byte offsets in dynamic SMEM
#define X_IDX  0        // src[128] @0, qry[128] @512
#define X_W0T  1024     // 256 floats, W0 transposed
#define X_B0   2048
#define X_B1   2304
#define X_B2   2560     // ends 2816
#define X_WT   2816     // 32768 B: W1H | W1L | W2H | W2L (matches g_wt layout)
#define X_W1H  (X_WT + 0)
#define X_W1L  (X_WT + 8192)
#define X_W2H  (X_WT + 16384)
#define X_W2L  (X_WT + 24576)
#define X_AH   35584    // 128 x 128B bf16 (SW128)
#define X_AL   51968    // ends 68352
#define X_K    2816     // fp32 k buffer overlay (WT + AH dead), 128 rows x 264B
#define SMEM_EDGE_BYTES 68352

// one GEMM layer: acc[2][8][4] += split-bf16( A[32wid..+31, 0:64] @ W[0:64]^T )
__device__ __forceinline__ void mma_layer(uint32_t sbAH, uint32_t sbAL,
                                          uint32_t sbWH, uint32_t sbWL,
                                          int wid, int lane, float acc[2][8][4]) {
    const int r7   = lane & 7;
    const int arow = r7 + (((lane >> 3) & 1) << 3);
    const int asel = lane >> 4;
    const int brow = r7 + ((lane >> 4) << 3);
    const int bsel = (lane >> 3) & 1;
#pragma unroll
    for (int ks = 0; ks < 4; ks++) {
        uint32_t ah[2][4], al[2][4];
#pragma unroll
        for (int mi = 0; mi < 2; mi++) {
            uint32_t off = (uint32_t)((32 * wid + mi * 16 + arow) * 128 +
                                      (((ks * 2 + asel) ^ r7) << 4));
            ldmx4(ah[mi][0], ah[mi][1], ah[mi][2], ah[mi][3], sbAH + off);
            ldmx4(al[mi][0], al[mi][1], al[mi][2], al[mi][3], sbAL + off);
        }
#pragma unroll
        for (int p = 0; p < 4; p++) {
            uint32_t woff = (uint32_t)((p * 16 + brow) * 128 +
                                       (((ks * 2 + bsel) ^ r7) << 4));
            uint32_t bh0, bh1, bh2, bh3, bl0, bl1, bl2, bl3;
            ldmx4(bh0, bh1, bh2, bh3, sbWH + woff);
            ldmx4(bl0, bl1, bl2, bl3, sbWL + woff);
#pragma unroll
            for (int mi = 0; mi < 2; mi++) {
                MMA16816(acc[mi][2 * p],     ah[mi][0], ah[mi][1], ah[mi][2], ah[mi][3], bh0, bh1);
                MMA16816(acc[mi][2 * p],     al[mi][0], al[mi][1], al[mi][2], al[mi][3], bh0, bh1);
                MMA16816(acc[mi][2 * p],     ah[mi][0], ah[mi][1], ah[mi][2], ah[mi][3], bl0, bl1);
                MMA16816(acc[mi][2 * p + 1], ah[mi][0], ah[mi][1], ah[mi][2], ah[mi][3], bh2, bh3);
                MMA16816(acc[mi][2 * p + 1], al[mi][0], al[mi][1], al[mi][2], al[mi][3], bh2, bh3);
                MMA16816(acc[mi][2 * p + 1], ah[mi][0], ah[mi][1], ah[mi][2], ah[mi][3], bl2, bl3);
            }
        }
    }
}

__global__ __launch_bounds__(128, 3) void edge_kernel(
    const float* __restrict__ latc, const float* __restrict__ qc,
    const float* __restrict__ rnd,
    const int* __restrict__ src, const int* __restrict__ qry,
    const float* __restrict__ Wk0, const float* __restrict__ bk0,
    const float* __restrict__ bk1, const float* __restrict__ bk2,
    int scale, int E)
{
    extern __shared__ char smc[];
    float* smf = (float*)smc;
    const uint32_t sb = smem_u32(smc);
    const int tid = threadIdx.x, wid = tid >> 5, lane = tid & 31;

    // ---- stage prepped weight tiles: straight uint4 copy (no conversion) ----
    {
        const uint4* gw = (const uint4*)g_wt;
        uint4* sw = (uint4*)(smc + X_WT);
#pragma unroll
        for (int i = 0; i < 16; i++) sw[tid + 128 * i] = gw[tid + 128 * i];
    }
    for (int i = tid; i < 256; i += 128) smf[(X_W0T >> 2) + (i & 63) * 4 + (i >> 6)] = Wk0[i];
    if (tid < 64) {
        smf[(X_B0 >> 2) + tid] = bk0[tid];
        smf[(X_B1 >> 2) + tid] = bk1[tid];
        smf[(X_B2 >> 2) + tid] = bk2[tid];
    }

    const int e = blockIdx.x * EPB + tid;
    int s = 0, q = -1;
    if (e < E) { s = src[e]; q = qry[e]; }
    int* sidx = (int*)(smc + X_IDX);
    sidx[tid] = s;
    sidx[EPB + tid] = q;
    float f0 = latc[2 * s], f1 = latc[2 * s + 1];
    float f2 = 0.f, f3 = 0.f;
    if (q >= 0) { f2 = qc[2 * q]; f3 = qc[2 * q + 1]; }
    __syncthreads();

    // ---- layer 1: 4 -> 64 per-thread, gelu, hi/lo split -> A tiles (own row) ----
    {
        const float4* w0 = (const float4*)(smc + X_W0T);
        const float* b0 = smf + (X_B0 >> 2);
#pragma unroll
        for (int c = 0; c < 8; c++) {
            float v[8];
#pragma unroll
            for (int jj = 0; jj < 8; jj++) {
                int j = c * 8 + jj;
                float4 w = w0[j];
                float a = b0[j];
                a = fmaf(f0, w.x, a); a = fmaf(f1, w.y, a);
                a = fmaf(f2, w.z, a); a = fmaf(f3, w.w, a);
                v[jj] = gelu_f(a);
            }
            uint32_t h[4], l[4];
#pragma unroll
            for (int m = 0; m < 4; m++) {
                h[m] = pkbf(v[2 * m], v[2 * m + 1]);
                float fx = __uint_as_float(h[m] << 16);
                float fy = __uint_as_float(h[m] & 0xFFFF0000u);
                l[m] = pkbf(v[2 * m] - fx, v[2 * m + 1] - fy);
            }
            uint32_t off = (uint32_t)(tid * 128 + ((c ^ (tid & 7)) << 4));
            *(uint4*)(smc + X_AH + off) = make_uint4(h[0], h[1], h[2], h[3]);
            *(uint4*)(smc + X_AL + off) = make_uint4(l[0], l[1], l[2], l[3]);
        }
    }
    __syncwarp();

    // ---- layer 2: MMA, then gelu + re-split in fragments (warp-own rows) ----
    float acc[2][8][4];
#pragma unroll
    for (int mi = 0; mi < 2; mi++)
#pragma unroll
        for (int ni = 0; ni < 8; ni++)
#pragma unroll
            for (int z = 0; z < 4; z++) acc[mi][ni][z] = 0.f;

    mma_layer(sb + X_AH, sb + X_AL, sb + X_W1H, sb + X_W1L, wid, lane, acc);

    {
        const float* b1 = smf + (X_B1 >> 2);
        const int g = lane >> 2, t = lane & 3;
#pragma unroll
        for (int mi = 0; mi < 2; mi++) {
            int row0 = 32 * wid + mi * 16 + g;
#pragma unroll
            for (int ni = 0; ni < 8; ni++) {
                float2 bb = *(const float2*)(b1 + ni * 8 + t * 2);
                float v0 = gelu_f(acc[mi][ni][0] + bb.x);
                float v1 = gelu_f(acc[mi][ni][1] + bb.y);
                float v2 = gelu_f(acc[mi][ni][2] + bb.x);
                float v3 = gelu_f(acc[mi][ni][3] + bb.y);
                uint32_t h0 = pkbf(v0, v1);
                uint32_t l0 = pkbf(v0 - __uint_as_float(h0 << 16),
                                   v1 - __uint_as_float(h0 & 0xFFFF0000u));
                uint32_t h1 = pkbf(v2, v3);
                uint32_t l1 = pkbf(v2 - __uint_as_float(h1 << 16),
                                   v3 - __uint_as_float(h1 & 0xFFFF0000u));
                int r1 = row0 + 8;
                uint32_t offA = (uint32_t)(row0 * 128 + ((ni ^ (row0 & 7)) << 4) + t * 4);
                uint32_t offB = (uint32_t)(r1 * 128 + ((ni ^ (r1 & 7)) << 4) + t * 4);
                *(uint32_t*)(smc + X_AH + offA) = h0;
                *(uint32_t*)(smc + X_AL + offA) = l0;
                *(uint32_t*)(smc + X_AH + offB) = h1;
                *(uint32_t*)(smc + X_AL + offB) = l1;
                acc[mi][ni][0] = 0.f; acc[mi][ni][1] = 0.f;
                acc[mi][ni][2] = 0.f; acc[mi][ni][3] = 0.f;
            }
        }
    }
    __syncwarp();

    // ---- layer 3: MMA (no activation) ----
    mma_layer(sb + X_AH, sb + X_AL, sb + X_W2H, sb + X_W2L, wid, lane, acc);
    __syncthreads();   // WT/A regions now dead everywhere; k buffer overlays them

    {
        const float* b2 = smf + (X_B2 >> 2);
        const int g = lane >> 2, t = lane & 3;
#pragma unroll
        for (int mi = 0; mi < 2; mi++) {
            int row0 = 32 * wid + mi * 16 + g;
#pragma unroll
            for (int ni = 0; ni < 8; ni++) {
                float2 bb = *(const float2*)(b2 + ni * 8 + t * 2);
                int colb = (ni * 8 + t * 2) * 4;
                *(float2*)(smc + X_K + row0 * 264 + colb) =
                    make_float2(acc[mi][ni][0] + bb.x, acc[mi][ni][1] + bb.y);
                *(float2*)(smc + X_K + (row0 + 8) * 264 + colb) =
                    make_float2(acc[mi][ni][2] + bb.x, acc[mi][ni][3] + bb.y);
            }
        }
    }
    __syncthreads();

    // ---- phase B: segmented reduction, chunk-of-8 prefetch for gather MLP ----
    const int b  = wid;
    const int c2 = lane;
    const float* rb = rnd + (size_t)b * N_LAT * CIN + 2 * c2;
    float* accBase = g_acc + ((size_t)(scale * BB + b) * N_QRY) * CIN + 2 * c2;
    float* cntBase = g_cnt + scale * N_QRY;

    float ax = 0.f, ay = 0.f;
    int prevq = -1, run = 0;
#pragma unroll 1
    for (int base = 0; base < EPB; base += 8) {
        float2 rr[8], kk[8];
        int qv[8];
#pragma unroll
        for (int j = 0; j < 8; j++) {
            int ss = sidx[base + j];
            qv[j] = sidx[EPB + base + j];
            rr[j] = *(const float2*)(rb + (size_t)ss * CIN);
            kk[j] = *(const float2*)(smc + X_K + (base + j) * 264 + c2 * 8);
        }
#pragma unroll
        for (int j = 0; j < 8; j++) {
            int qq = qv[j];
            if (qq != prevq) {
                if (prevq >= 0) {
                    float* d = accBase + (size_t)prevq * CIN;
                    atomicAdd(d, ax);
                    atomicAdd(d + 1, ay);
                    if (tid == 0) atomicAdd(cntBase + prevq, (float)run);
                }
                ax = 0.f; ay = 0.f; run = 0; prevq = qq;
            }
            if (qq >= 0) {
                ax = fmaf(kk[j].x, rr[j].x, ax);
                ay = fmaf(kk[j].y, rr[j].y, ay);
                run++;
            }
        }
    }
    if (prevq >= 0) {
        float* d = accBase + (size_t)prevq * CIN;
        atomicAdd(d, ax);
        atomicAdd(d + 1, ay);
        if (tid == 0) atomicAdd(cntBase + prevq, (float)run);
    }
}

// ---------------- kernel 3: combine scales + projection MLP ----------------------
#define OCWP0 0
#define OCBP0 16384
#define OCWP1 16640
#define OCBP1 17664
#define OCDEC 17668
#define SMEM_COMB_FLOATS (OCDEC + 8 * 64)  // 18180 floats = 72720 B
#define CTASKS 8

__global__ __launch_bounds__(256) void combine_kernel(
    const float* __restrict__ Wp0, const float* __restrict__ bp0,
    const float* __restrict__ Wp1, const float* __restrict__ bp1,
    float* __restrict__ out)
{
    extern __shared__ float sm[];
    const int tid = threadIdx.x;
    for (int i = tid; i < 16384; i += 256) sm[OCWP0 + i] = Wp0[i];
    for (int i = tid; i < 256;   i += 256) sm[OCBP0 + i] = bp0[i];
    for (int i = tid; i < 1024;  i += 256) sm[OCWP1 + i] = Wp1[i];
    if (tid < 4) sm[OCBP1 + tid] = bp1[tid];
    __syncthreads();

    const int warp = tid >> 5, lane = tid & 31;
    float* sdec = sm + OCDEC + warp * 64;
    const int tbase = (blockIdx.x * 8 + warp) * CTASKS;
    const size_t scale_stride = (size_t)BB * N_QRY * CIN;

    for (int it = 0; it < CTASKS; it++) {
        int t = tbase + it;
        int b = t >> 14;          // / N_QRY
        int q = t & (N_QRY - 1);

        float w0 = g_w[2 * q], w1 = g_w[2 * q + 1];
        float i0 = w0 / fmaxf(g_cnt[q], 1.f);
        float i1 = w1 / fmaxf(g_cnt[N_QRY + q], 1.f);
        size_t base0 = ((size_t)b * N_QRY + q) * CIN;
        size_t base1 = base0 + scale_stride;

        __syncwarp();
        sdec[lane]      = fmaf(i0, g_acc[base0 + lane],      i1 * g_acc[base1 + lane]);
        sdec[lane + 32] = fmaf(i0, g_acc[base0 + lane + 32], i1 * g_acc[base1 + lane + 32]);
        __syncwarp();

        const int u0 = lane * 8;
        // packed FFMA2 accumulators, fully unrolled ILP (was: unroll 1, scalar)
        unsigned long long A0, A1, A2, A3;
        {
            const unsigned long long* bb = (const unsigned long long*)(sm + OCBP0 + u0);
            A0 = bb[0]; A1 = bb[1]; A2 = bb[2]; A3 = bb[3];
        }
#pragma unroll 4
        for (int k = 0; k < 64; k++) {
            unsigned long long xk2 = dup2(sdec[k]);
            const ulonglong2* wr = (const ulonglong2*)(sm + OCWP0 + k * 256 + u0);
            ulonglong2 wa = wr[0], wb = wr[1];
            A0 = fma2(xk2, wa.x, A0);
            A1 = fma2(xk2, wa.y, A1);
            A2 = fma2(xk2, wb.x, A2);
            A3 = fma2(xk2, wb.y, A3);
        }
        float a[8];
        {
            float2 p;
            p = unpk2(A0); a[0] = p.x; a[1] = p.y;
            p = unpk2(A1); a[2] = p.x; a[3] = p.y;
            p = unpk2(A2); a[4] = p.x; a[5] = p.y;
            p = unpk2(A3); a[6] = p.x; a[7] = p.y;
        }
        float4 o = make_float4(0.f, 0.f, 0.f, 0.f);
#pragma unroll
        for (int j = 0; j < 8; j++) {
            float hg = gelu_f(a[j]);
            float4 wp = ((const float4*)(sm + OCWP1))[u0 + j];
            o.x = fmaf(hg, wp.x, o.x); o.y = fmaf(hg, wp.y, o.y);
            o.z = fmaf(hg, wp.z, o.z); o.w = fmaf(hg, wp.w, o.w);
        }
#pragma unroll
        for (int off = 16; off > 0; off >>= 1) {
            o.x += __shfl_xor_sync(0xffffffffu, o.x, off);
            o.y += __shfl_xor_sync(0xffffffffu, o.y, off);
            o.z += __shfl_xor_sync(0xffffffffu, o.z, off);
            o.w += __shfl_xor_sync(0xffffffffu, o.w, off);
        }
        if (lane == 0) {
            float4 r;
            r.x = o.x + sm[OCBP1 + 0];
            r.y = o.y + sm[OCBP1 + 1];
            r.z = o.z + sm[OCBP1 + 2];
            r.w = o.w + sm[OCBP1 + 3];
            ((float4*)out)[(size_t)b * N_QRY + q] = r;
        }
    }
}

// ---------------- launch ---------------------------------------------------------
extern "C" void kernel_launch(void* const* d_in, const int* in_sizes, int n_in,
                              void* d_out, int out_size)
{
    const float* latc = (const float*)d_in[0];
    const float* rnd  = (const float*)d_in[1];
    const float* qc   = (const float*)d_in[2];
    const int*   src0 = (const int*)d_in[3];
    const int*   qry0 = (const int*)d_in[4];
    const int*   src1 = (const int*)d_in[5];
    const int*   qry1 = (const int*)d_in[6];
    const float* Wk0  = (const float*)d_in[7];
    const float* bk0  = (const float*)d_in[8];
    const float* Wk1  = (const float*)d_in[9];
    const float* bk1  = (const float*)d_in[10];
    const float* Wk2  = (const float*)d_in[11];
    const float* bk2  = (const float*)d_in[12];
    const float* Wsw0 = (const float*)d_in[13];
    const float* bsw0 = (const float*)d_in[14];
    const float* Wsw1 = (const float*)d_in[15];
    const float* bsw1 = (const float*)d_in[16];
    const float* Wp0  = (const float*)d_in[17];
    const float* bp0  = (const float*)d_in[18];
    const float* Wp1  = (const float*)d_in[19];
    const float* bp1  = (const float*)d_in[20];

    const int E0 = in_sizes[3];
    const int E1 = in_sizes[5];

    const size_t smemC = SMEM_COMB_FLOATS * sizeof(float);
    cudaFuncSetAttribute(edge_kernel,    cudaFuncAttributeMaxDynamicSharedMemorySize, SMEM_EDGE_BYTES);
    cudaFuncSetAttribute(combine_kernel, cudaFuncAttributeMaxDynamicSharedMemorySize, (int)smemC);

    zero_kernel<<<1024, 256>>>();
    prep_kernel<<<16, 256>>>(Wk1, Wk2);
    switch_kernel<<<(N_QRY + 255) / 256, 256>>>(qc, Wsw0, bsw0, Wsw1, bsw1);
    edge_kernel<<<(E0 + EPB - 1) / EPB, 128, SMEM_EDGE_BYTES>>>(latc, qc, rnd, src0, qry0,
                                                                Wk0, bk0, bk1, bk2, 0, E0);
    edge_kernel<<<(E1 + EPB - 1) / EPB, 128, SMEM_EDGE_BYTES>>>(latc, qc, rnd, src1, qry1,
                                                                Wk0, bk0, bk1, bk2, 1, E1);
    combine_kernel<<<1024, 256, smemC>>>(Wp0, bp0, Wp1, bp1, (float*)d_out);
}

// round 14
// speedup vs baseline: 4.0605x; 1.9558x over previous
#include <cuda_runtime.h>
#include <cuda_bf16.h>
#include <cstdint>

#define N_LAT 4096
#define N_QRY 16384
#define BB    4
#define CIN   64

// ---------------- scratch (device globals: allocation-free rule) ----------------
__device__ float g_acc[2 * BB * N_QRY * CIN];   // [scale][b][q][c], 33.5 MB
__device__ float g_cnt[2 * N_QRY];              // edge counts per query per scale
__device__ float g_w[N_QRY * 2];                // softmax switch weights
__device__ unsigned char g_wt[32768];           // W1H|W1L|W2H|W2L swizzled bf16 tiles
__device__ unsigned char g_wt2[65536];          // Wp0^T hi (32KB) | lo (32KB) swizzled

// ---------------- helpers --------------------------------------------------------
__device__ __forceinline__ uint32_t pkbf(float a, float b) {
    __nv_bfloat162 t = __floats2bfloat162_rn(a, b);
    return *reinterpret_cast<uint32_t*>(&t);
}
__device__ __forceinline__ float gelu_f(float x) {
    float x2 = x * x;
    float y  = 0.7978845608028654f * x * fmaf(0.044715f, x2, 1.0f);
    float e  = __expf(2.0f * y);
    float t  = 1.0f - __fdividef(2.0f, e + 1.0f); // == tanh(y)
    return 0.5f * x * (1.0f + t);
}
__device__ __forceinline__ uint32_t smem_u32(const void* p) {
    uint32_t a;
    asm("{ .reg .u64 t; cvta.to.shared.u64 t, %1; cvt.u32.u64 %0, t; }" : "=r"(a) : "l"(p));
    return a;
}
__device__ __forceinline__ void ldmx4(uint32_t& r0, uint32_t& r1, uint32_t& r2, uint32_t& r3,
                                      uint32_t addr) {
    asm volatile("ldmatrix.sync.aligned.m8n8.x4.shared.b16 {%0,%1,%2,%3}, [%4];"
                 : "=r"(r0), "=r"(r1), "=r"(r2), "=r"(r3) : "r"(addr));
}
#define MMA16816(c, a0, a1, a2, a3, b0, b1)                                   \
    asm volatile("mma.sync.aligned.m16n8k16.row.col.f32.bf16.bf16.f32 "       \
                 "{%0,%1,%2,%3}, {%4,%5,%6,%7}, {%8,%9}, {%0,%1,%2,%3};"      \
                 : "+f"((c)[0]), "+f"((c)[1]), "+f"((c)[2]), "+f"((c)[3])     \
                 : "r"(a0), "r"(a1), "r"(a2), "r"(a3), "r"(b0), "r"(b1))

// ---------------- kernel 0: zero accumulators -----------------------------------
__global__ void zero_kernel() {
    const size_t n4 = (size_t)(2 * BB * N_QRY * CIN) / 4;
    float4* p = (float4*)g_acc;
    const float4 z = make_float4(0.f, 0.f, 0.f, 0.f);
    for (size_t i = (size_t)blockIdx.x * blockDim.x + threadIdx.x; i < n4;
         i += (size_t)gridDim.x * blockDim.x)
        p[i] = z;
    for (int i = blockIdx.x * blockDim.x + threadIdx.x; i < 2 * N_QRY;
         i += gridDim.x * blockDim.x)
        g_cnt[i] = 0.f;
}

// ---------------- prep kernel: swizzled bf16 hi/lo tiles for Wk1/Wk2/Wp0 ---------
__global__ void prep_kernel(const float* __restrict__ Wk1, const float* __restrict__ Wk2,
                            const float* __restrict__ Wp0) {
    int i = blockIdx.x * blockDim.x + threadIdx.x;   // 0..16383
    if (i < 4096) {
        int j = i & 63, k = i >> 6;
        uint32_t off = (uint32_t)(j * 128 + (((k >> 3) ^ (j & 7)) << 4) + (k & 7) * 2);
        float w1 = Wk1[i];
        __nv_bfloat16 h1 = __float2bfloat16_rn(w1);
        *(__nv_bfloat16*)(g_wt + 0     + off) = h1;
        *(__nv_bfloat16*)(g_wt + 8192  + off) = __float2bfloat16_rn(w1 - __bfloat162float(h1));
        float w2 = Wk2[i];
        __nv_bfloat16 h2 = __float2bfloat16_rn(w2);
        *(__nv_bfloat16*)(g_wt + 16384 + off) = h2;
        *(__nv_bfloat16*)(g_wt + 24576 + off) = __float2bfloat16_rn(w2 - __bfloat162float(h2));
    }
    if (i < 16384) {
        int n = i & 255, k = i >> 8;                 // Wp0[k][n], k<64, n<256
        float w = Wp0[k * 256 + n];
        __nv_bfloat16 h = __float2bfloat16_rn(w);
        uint32_t off = (uint32_t)(n * 128 + (((k >> 3) ^ (n & 7)) << 4) + (k & 7) * 2);
        *(__nv_bfloat16*)(g_wt2 + off) = h;
        *(__nv_bfloat16*)(g_wt2 + 32768 + off) = __float2bfloat16_rn(w - __bfloat162float(h));
    }
}

// ---------------- kernel 1: switch MLP + softmax --------------------------------
__global__ void switch_kernel(const float* __restrict__ qc,
                              const float* __restrict__ Wsw0, const float* __restrict__ bsw0,
                              const float* __restrict__ Wsw1, const float* __restrict__ bsw1) {
    int q = blockIdx.x * blockDim.x + threadIdx.x;
    if (q >= N_QRY) return;
    float x0 = qc[2 * q], x1 = qc[2 * q + 1];
    float l0 = bsw1[0], l1 = bsw1[1];
#pragma unroll
    for (int j = 0; j < 16; j++) {
        float hv = bsw0[j];
        hv = fmaf(x0, Wsw0[j], hv);
        hv = fmaf(x1, Wsw0[16 + j], hv);
        hv = fmaxf(hv, 0.f);
        l0 = fmaf(hv, Wsw1[2 * j], l0);
        l1 = fmaf(hv, Wsw1[2 * j + 1], l1);
    }
    float m = fmaxf(l0, l1);
    float e0 = expf(l0 - m), e1 = expf(l1 - m);
    float inv = 1.f / (e0 + e1);
    g_w[2 * q]     = e0 * inv;
    g_w[2 * q + 1] = e1 * inv;
}

// ---------------- shared GEMM core: acc += split-bf16(A[32wid..][64] @ W[64][64]^T)
__device__ __forceinline__ void mma_layer(uint32_t sbAH, uint32_t sbAL,
                                          uint32_t sbWH, uint32_t sbWL,
                                          int wid, int lane, float acc[2][8][4]) {
    const int r7   = lane & 7;
    const int arow = r7 + (((lane >> 3) & 1) << 3);
    const int asel = lane >> 4;
    const int brow = r7 + ((lane >> 4) << 3);
    const int bsel = (lane >> 3) & 1;
#pragma unroll
    for (int ks = 0; ks < 4; ks++) {
        uint32_t ah[2][4], al[2][4];
#pragma unroll
        for (int mi = 0; mi < 2; mi++) {
            uint32_t off = (uint32_t)((32 * wid + mi * 16 + arow) * 128 +
                                      (((ks * 2 + asel) ^ r7) << 4));
            ldmx4(ah[mi][0], ah[mi][1], ah[mi][2], ah[mi][3], sbAH + off);
            ldmx4(al[mi][0], al[mi][1], al[mi][2], al[mi][3], sbAL + off);
        }
#pragma unroll
        for (int p = 0; p < 4; p++) {
            uint32_t woff = (uint32_t)((p * 16 + brow) * 128 +
                                       (((ks * 2 + bsel) ^ r7) << 4));
            uint32_t bh0, bh1, bh2, bh3, bl0, bl1, bl2, bl3;
            ldmx4(bh0, bh1, bh2, bh3, sbWH + woff);
            ldmx4(bl0, bl1, bl2, bl3, sbWL + woff);
#pragma unroll
            for (int mi = 0; mi < 2; mi++) {
                MMA16816(acc[mi][2 * p],     ah[mi][0], ah[mi][1], ah[mi][2], ah[mi][3], bh0, bh1);
                MMA16816(acc[mi][2 * p],     al[mi][0], al[mi][1], al[mi][2], al[mi][3], bh0, bh1);
                MMA16816(acc[mi][2 * p],     ah[mi][0], ah[mi][1], ah[mi][2], ah[mi][3], bl0, bl1);
                MMA16816(acc[mi][2 * p + 1], ah[mi][0], ah[mi][1], ah[mi][2], ah[mi][3], bh2, bh3);
                MMA16816(acc[mi][2 * p + 1], al[mi][0], al[mi][1], al[mi][2], al[mi][3], bh2, bh3);
                MMA16816(acc[mi][2 * p + 1], ah[mi][0], ah[mi][1], ah[mi][2], ah[mi][3], bl2, bl3);
            }
        }
    }
}

// ---------------- kernel 2: HMMA edge MLP + segmented reduction ------------------
#define EPB 128
#define X_IDX  0
#define X_W0T  1024
#define X_B0   2048
#define X_B1   2304
#define X_B2   2560
#define X_WT   2816
#define X_W1H  (X_WT + 0)
#define X_W1L  (X_WT + 8192)
#define X_W2H  (X_WT + 16384)
#define X_W2L  (X_WT + 24576)
#define X_AH   35584
#define X_AL   51968
#define X_K    2816
#define SMEM_EDGE_BYTES 68352

__global__ __launch_bounds__(128, 3) void edge_kernel(
    const float* __restrict__ latc, const float* __restrict__ qc,
    const float* __restrict__ rnd,
    const int* __restrict__ src, const int* __restrict__ qry,
    const float* __restrict__ Wk0, const float* __restrict__ bk0,
    const float* __restrict__ bk1, const float* __restrict__ bk2,
    int scale, int E)
{
    extern __shared__ char smc[];
    float* smf = (float*)smc;
    const uint32_t sb = smem_u32(smc);
    const int tid = threadIdx.x, wid = tid >> 5, lane = tid & 31;

    {
        const uint4* gw = (const uint4*)g_wt;
        uint4* sw = (uint4*)(smc + X_WT);
#pragma unroll
        for (int i = 0; i < 16; i++) sw[tid + 128 * i] = gw[tid + 128 * i];
    }
    for (int i = tid; i < 256; i += 128) smf[(X_W0T >> 2) + (i & 63) * 4 + (i >> 6)] = Wk0[i];
    if (tid < 64) {
        smf[(X_B0 >> 2) + tid] = bk0[tid];
        smf[(X_B1 >> 2) + tid] = bk1[tid];
        smf[(X_B2 >> 2) + tid] = bk2[tid];
    }

    const int e = blockIdx.x * EPB + tid;
    int s = 0, q = -1;
    if (e < E) { s = src[e]; q = qry[e]; }
    int* sidx = (int*)(smc + X_IDX);
    sidx[tid] = s;
    sidx[EPB + tid] = q;
    float f0 = latc[2 * s], f1 = latc[2 * s + 1];
    float f2 = 0.f, f3 = 0.f;
    if (q >= 0) { f2 = qc[2 * q]; f3 = qc[2 * q + 1]; }
    __syncthreads();

    // layer 1: 4 -> 64 per-thread, gelu, hi/lo split -> A tiles
    {
        const float4* w0 = (const float4*)(smc + X_W0T);
        const float* b0 = smf + (X_B0 >> 2);
#pragma unroll
        for (int c = 0; c < 8; c++) {
            float v[8];
#pragma unroll
            for (int jj = 0; jj < 8; jj++) {
                int j = c * 8 + jj;
                float4 w = w0[j];
                float a = b0[j];
                a = fmaf(f0, w.x, a); a = fmaf(f1, w.y, a);
                a = fmaf(f2, w.z, a); a = fmaf(f3, w.w, a);
                v[jj] = gelu_f(a);
            }
            uint32_t h[4], l[4];
#pragma unroll
            for (int m = 0; m < 4; m++) {
                h[m] = pkbf(v[2 * m], v[2 * m + 1]);
                float fx = __uint_as_float(h[m] << 16);
                float fy = __uint_as_float(h[m] & 0xFFFF0000u);
                l[m] = pkbf(v[2 * m] - fx, v[2 * m + 1] - fy);
            }
            uint32_t off = (uint32_t)(tid * 128 + ((c ^ (tid & 7)) << 4));
            *(uint4*)(smc + X_AH + off) = make_uint4(h[0], h[1], h[2], h[3]);
            *(uint4*)(smc + X_AL + off) = make_uint4(l[0], l[1], l[2], l[3]);
        }
    }
    __syncwarp();

    float acc[2][8][4];
#pragma unroll
    for (int mi = 0; mi < 2; mi++)
#pragma unroll
        for (int ni = 0; ni < 8; ni++)
#pragma unroll
            for (int z = 0; z < 4; z++) acc[mi][ni][z] = 0.f;

    mma_layer(sb + X_AH, sb + X_AL, sb + X_W1H, sb + X_W1L, wid, lane, acc);

    {
        const float* b1 = smf + (X_B1 >> 2);
        const int g = lane >> 2, t = lane & 3;
#pragma unroll
        for (int mi = 0; mi < 2; mi++) {
            int row0 = 32 * wid + mi * 16 + g;
#pragma unroll
            for (int ni = 0; ni < 8; ni++) {
                float2 bb = *(const float2*)(b1 + ni * 8 + t * 2);
                float v0 = gelu_f(acc[mi][ni][0] + bb.x);
                float v1 = gelu_f(acc[mi][ni][1] + bb.y);
                float v2 = gelu_f(acc[mi][ni][2] + bb.x);
                float v3 = gelu_f(acc[mi][ni][3] + bb.y);
                uint32_t h0 = pkbf(v0, v1);
                uint32_t l0 = pkbf(v0 - __uint_as_float(h0 << 16),
                                   v1 - __uint_as_float(h0 & 0xFFFF0000u));
                uint32_t h1 = pkbf(v2, v3);
                uint32_t l1 = pkbf(v2 - __uint_as_float(h1 << 16),
                                   v3 - __uint_as_float(h1 & 0xFFFF0000u));
                int r1 = row0 + 8;
                uint32_t offA = (uint32_t)(row0 * 128 + ((ni ^ (row0 & 7)) << 4) + t * 4);
                uint32_t offB = (uint32_t)(r1 * 128 + ((ni ^ (r1 & 7)) << 4) + t * 4);
                *(uint32_t*)(smc + X_AH + offA) = h0;
                *(uint32_t*)(smc + X_AL + offA) = l0;
                *(uint32_t*)(smc + X_AH + offB) = h1;
                *(uint32_t*)(smc + X_AL + offB) = l1;
                acc[mi][ni][0] = 0.f; acc[mi][ni][1] = 0.f;
                acc[mi][ni][2] = 0.f; acc[mi][ni][3] = 0.f;
            }
        }
    }
    __syncwarp();

    mma_layer(sb + X_AH, sb + X_AL, sb + X_W2H, sb + X_W2L, wid, lane, acc);
    __syncthreads();

    {
        const float* b2 = smf + (X_B2 >> 2);
        const int g = lane >> 2, t = lane & 3;
#pragma unroll
        for (int mi = 0; mi < 2; mi++) {
            int row0 = 32 * wid + mi * 16 + g;
#pragma unroll
            for (int ni = 0; ni < 8; ni++) {
                float2 bb = *(const float2*)(b2 + ni * 8 + t * 2);
                int colb = (ni * 8 + t * 2) * 4;
                *(float2*)(smc + X_K + row0 * 264 + colb) =
                    make_float2(acc[mi][ni][0] + bb.x, acc[mi][ni][1] + bb.y);
                *(float2*)(smc + X_K + (row0 + 8) * 264 + colb) =
                    make_float2(acc[mi][ni][2] + bb.x, acc[mi][ni][3] + bb.y);
            }
        }
    }
    __syncthreads();

    // phase B: segmented reduction, chunk-of-8 prefetch
    const int b  = wid;
    const int c2 = lane;
    const float* rb = rnd + (size_t)b * N_LAT * CIN + 2 * c2;
    float* accBase = g_acc + ((size_t)(scale * BB + b) * N_QRY) * CIN + 2 * c2;
    float* cntBase = g_cnt + scale * N_QRY;

    float ax = 0.f, ay = 0.f;
    int prevq = -1, run = 0;
#pragma unroll 1
    for (int base = 0; base < EPB; base += 8) {
        float2 rr[8], kk[8];
        int qv[8];
#pragma unroll
        for (int j = 0; j < 8; j++) {
            int ss = sidx[base + j];
            qv[j] = sidx[EPB + base + j];
            rr[j] = *(const float2*)(rb + (size_t)ss * CIN);
            kk[j] = *(const float2*)(smc + X_K + (base + j) * 264 + c2 * 8);
        }
#pragma unroll
        for (int j = 0; j < 8; j++) {
            int qq = qv[j];
            if (qq != prevq) {
                if (prevq >= 0) {
                    float* d = accBase + (size_t)prevq * CIN;
                    atomicAdd(d, ax);
                    atomicAdd(d + 1, ay);
                    if (tid == 0) atomicAdd(cntBase + prevq, (float)run);
                }
                ax = 0.f; ay = 0.f; run = 0; prevq = qq;
            }
            if (qq >= 0) {
                ax = fmaf(kk[j].x, rr[j].x, ax);
                ay = fmaf(kk[j].y, rr[j].y, ay);
                run++;
            }
        }
    }
    if (prevq >= 0) {
        float* d = accBase + (size_t)prevq * CIN;
        atomicAdd(d, ax);
        atomicAdd(d + 1, ay);
        if (tid == 0) atomicAdd(cntBase + prevq, (float)run);
    }
}

// ---------------- kernel 3: HMMA combine + projection MLP ------------------------
// Block = 128 rows of decoded (65536 total). Warp owns 32 rows.
// Stage decoded -> bf16 hi/lo A tiles; 4 N-chunks of 64: 3-term MMA vs Wp0^T,
// bias+gelu in fragments, Wp1 accumulated into per-thread out[4][4]; quad shfl
// reduce; float4 store.
#define CM_WTH  0          // 32768 B Wp0^T hi
#define CM_WTL  32768      // 32768 B Wp0^T lo
#define CM_AH   65536      // 16384 B
#define CM_AL   81920      // 16384 B
#define CM_WP1  98304      // 4096 B (256 x float4)
#define CM_BP0  102400     // 1024 B
#define CM_BP1  103424     // 16 B
#define SMEM_COMB_BYTES 103440

__global__ __launch_bounds__(128) void combine_kernel(
    const float* __restrict__ bp0, const float* __restrict__ Wp1,
    const float* __restrict__ bp1, float* __restrict__ out)
{
    extern __shared__ char smc[];
    float* smf = (float*)smc;
    const uint32_t sb = smem_u32(smc);
    const int tid = threadIdx.x, wid = tid >> 5, lane = tid & 31;
    const int g = lane >> 2, t4 = lane & 3;

    // stage prepped Wp0^T tiles + Wp1 + biases
    {
        const uint4* gw = (const uint4*)g_wt2;
        uint4* sw = (uint4*)(smc + CM_WTH);
#pragma unroll
        for (int i = 0; i < 32; i++) sw[tid + 128 * i] = gw[tid + 128 * i];
    }
    for (int i = tid; i < 256; i += 128) ((uint4*)(smc + CM_WP1))[i] = ((const uint4*)Wp1)[i];
    if (tid < 64) ((uint4*)(smc + CM_BP0))[tid] = ((const uint4*)bp0)[tid];
    if (tid < 4) smf[(CM_BP1 >> 2) + tid] = bp1[tid];

    // stage decoded rows -> bf16 hi/lo A tiles (warp-local rows; lane = channel)
    const int R = blockIdx.x * 128;
    {
        const size_t ss = (size_t)BB * N_QRY * CIN;
#pragma unroll 2
        for (int i = 0; i < 32; i++) {
            int lr = wid * 32 + i;
            int r = R + lr;
            int q = r & (N_QRY - 1);
            int b = r >> 14;
            float i0 = __fdividef(g_w[2 * q],     fmaxf(g_cnt[q], 1.f));
            float i1 = __fdividef(g_w[2 * q + 1], fmaxf(g_cnt[N_QRY + q], 1.f));
            size_t base0 = ((size_t)b * N_QRY + q) * CIN;
            size_t base1 = base0 + ss;
            float v  = fmaf(i0, g_acc[base0 + lane],      i1 * g_acc[base1 + lane]);
            float v2 = fmaf(i0, g_acc[base0 + lane + 32], i1 * g_acc[base1 + lane + 32]);
            __nv_bfloat16 h  = __float2bfloat16_rn(v);
            __nv_bfloat16 h2 = __float2bfloat16_rn(v2);
            uint32_t o1 = (uint32_t)(lr * 128 + (((lane >> 3) ^ (lr & 7)) << 4) + (lane & 7) * 2);
            uint32_t o2 = (uint32_t)(lr * 128 + ((((lane + 32) >> 3) ^ (lr & 7)) << 4) + (lane & 7) * 2);
            *(__nv_bfloat16*)(smc + CM_AH + o1) = h;
            *(__nv_bfloat16*)(smc + CM_AL + o1) = __float2bfloat16_rn(v - __bfloat162float(h));
            *(__nv_bfloat16*)(smc + CM_AH + o2) = h2;
            *(__nv_bfloat16*)(smc + CM_AL + o2) = __float2bfloat16_rn(v2 - __bfloat162float(h2));
        }
    }
    __syncthreads();

    float o_[4][4];
#pragma unroll
    for (int a = 0; a < 4; a++)
#pragma unroll
        for (int c = 0; c < 4; c++) o_[a][c] = 0.f;

    float acc[2][8][4];
    const float* bp0s = smf + (CM_BP0 >> 2);
    const float4* wp1s = (const float4*)(smc + CM_WP1);

#pragma unroll 1
    for (int c = 0; c < 4; c++) {
#pragma unroll
        for (int mi = 0; mi < 2; mi++)
#pragma unroll
            for (int ni = 0; ni < 8; ni++)
#pragma unroll
                for (int z = 0; z < 4; z++) acc[mi][ni][z] = 0.f;

        mma_layer(sb + CM_AH, sb + CM_AL,
                  sb + CM_WTH + c * 8192, sb + CM_WTL + c * 8192, wid, lane, acc);

#pragma unroll
        for (int ni = 0; ni < 8; ni++) {
            int col0 = c * 64 + ni * 8 + t4 * 2;
            float2 bb = *(const float2*)(bp0s + col0);
            float4 wA = wp1s[col0];
            float4 wB = wp1s[col0 + 1];
#pragma unroll
            for (int mi = 0; mi < 2; mi++) {
                float v0 = gelu_f(acc[mi][ni][0] + bb.x);
                float v1 = gelu_f(acc[mi][ni][1] + bb.y);
                float v2 = gelu_f(acc[mi][ni][2] + bb.x);
                float v3 = gelu_f(acc[mi][ni][3] + bb.y);
                float* oa = o_[mi * 2];
                oa[0] = fmaf(v0, wA.x, oa[0]); oa[1] = fmaf(v0, wA.y, oa[1]);
                oa[2] = fmaf(v0, wA.z, oa[2]); oa[3] = fmaf(v0, wA.w, oa[3]);
                oa[0] = fmaf(v1, wB.x, oa[0]); oa[1] = fmaf(v1, wB.y, oa[1]);
                oa[2] = fmaf(v1, wB.z, oa[2]); oa[3] = fmaf(v1, wB.w, oa[3]);
                float* ob = o_[mi * 2 + 1];
                ob[0] = fmaf(v2, wA.x, ob[0]); ob[1] = fmaf(v2, wA.y, ob[1]);
                ob[2] = fmaf(v2, wA.z, ob[2]); ob[3] = fmaf(v2, wA.w, ob[3]);
                ob[0] = fmaf(v3, wB.x, ob[0]); ob[1] = fmaf(v3, wB.y, ob[1]);
                ob[2] = fmaf(v3, wB.z, ob[2]); ob[3] = fmaf(v3, wB.w, ob[3]);
            }
        }
    }

    // reduce across the 4 lanes of each row quad, add bp1, store
#pragma unroll
    for (int rI = 0; rI < 4; rI++)
#pragma unroll
        for (int cc = 0; cc < 4; cc++) {
            float v = o_[rI][cc];
            v += __shfl_xor_sync(0xffffffffu, v, 1);
            v += __shfl_xor_sync(0xffffffffu, v, 2);
            o_[rI][cc] = v;
        }
    if (t4 == 0) {
        const float* b1 = smf + (CM_BP1 >> 2);
#pragma unroll
        for (int rI = 0; rI < 4; rI++) {
            int row = R + 32 * wid + g + (rI >> 1) * 16 + (rI & 1) * 8;
            float4 r4;
            r4.x = o_[rI][0] + b1[0];
            r4.y = o_[rI][1] + b1[1];
            r4.z = o_[rI][2] + b1[2];
            r4.w = o_[rI][3] + b1[3];
            ((float4*)out)[row] = r4;
        }
    }
}

// ---------------- launch ---------------------------------------------------------
extern "C" void kernel_launch(void* const* d_in, const int* in_sizes, int n_in,
                              void* d_out, int out_size)
{
    const float* latc = (const float*)d_in[0];
    const float* rnd  = (const float*)d_in[1];
    const float* qc   = (const float*)d_in[2];
    const int*   src0 = (const int*)d_in[3];
    const int*   qry0 = (const int*)d_in[4];
    const int*   src1 = (const int*)d_in[5];
    const int*   qry1 = (const int*)d_in[6];
    const float* Wk0  = (const float*)d_in[7];
    const float* bk0  = (const float*)d_in[8];
    const float* Wk1  = (const float*)d_in[9];
    const float* bk1  = (const float*)d_in[10];
    const float* Wk2  = (const float*)d_in[11];
    const float* bk2  = (const float*)d_in[12];
    const float* Wsw0 = (const float*)d_in[13];
    const float* bsw0 = (const float*)d_in[14];
    const float* Wsw1 = (const float*)d_in[15];
    const float* bsw1 = (const float*)d_in[16];
    const float* Wp0  = (const float*)d_in[17];
    const float* bp0  = (const float*)d_in[18];
    const float* Wp1  = (const float*)d_in[19];
    const float* bp1  = (const float*)d_in[20];

    const int E0 = in_sizes[3];
    const int E1 = in_sizes[5];

    cudaFuncSetAttribute(edge_kernel,    cudaFuncAttributeMaxDynamicSharedMemorySize, SMEM_EDGE_BYTES);
    cudaFuncSetAttribute(combine_kernel, cudaFuncAttributeMaxDynamicSharedMemorySize, SMEM_COMB_BYTES);

    zero_kernel<<<1024, 256>>>();
    prep_kernel<<<64, 256>>>(Wk1, Wk2, Wp0);
    switch_kernel<<<(N_QRY + 255) / 256, 256>>>(qc, Wsw0, bsw0, Wsw1, bsw1);
    edge_kernel<<<(E0 + EPB - 1) / EPB, 128, SMEM_EDGE_BYTES>>>(latc, qc, rnd, src0, qry0,
                                                                Wk0, bk0, bk1, bk2, 0, E0);
    edge_kernel<<<(E1 + EPB - 1) / EPB, 128, SMEM_EDGE_BYTES>>>(latc, qc, rnd, src1, qry1,
                                                                Wk0, bk0, bk1, bk2, 1, E1);
    combine_kernel<<<512, 128, SMEM_COMB_BYTES>>>(bp0, Wp1, bp1, (float*)d_out);
}

// round 15
// speedup vs baseline: 4.6873x; 1.1544x over previous
#include <cuda_runtime.h>
#include <cuda_bf16.h>
#include <cstdint>

#define N_LAT 4096
#define N_QRY 16384
#define BB    4
#define CIN   64

// ---------------- scratch (device globals: allocation-free rule) ----------------
__device__ float g_acc[2 * BB * N_QRY * CIN];   // [scale][b][q][c], 33.5 MB
__device__ float g_cnt[2 * N_QRY];              // edge counts per query per scale
__device__ float g_w[N_QRY * 2];                // softmax switch weights
__device__ unsigned char g_wt[32768];           // W1H|W1L|W2H|W2L swizzled bf16 tiles
__device__ unsigned char g_wt2[65536];          // Wp0^T hi (32KB) | lo (32KB) swizzled

// ---------------- helpers --------------------------------------------------------
__device__ __forceinline__ uint32_t pkbf(float a, float b) {
    __nv_bfloat162 t = __floats2bfloat162_rn(a, b);
    return *reinterpret_cast<uint32_t*>(&t);
}
// fast gelu: MUFU.TANH (1 MUFU, ~5 FMA) — cutlass fast_tanh path
__device__ __forceinline__ float gelu_f(float x) {
    float y = 0.7978845608028654f * fmaf(0.044715f, x * x, 1.0f) * x;
    float t;
    asm("tanh.approx.f32 %0, %1;" : "=f"(t) : "f"(y));
    float h = 0.5f * x;
    return fmaf(h, t, h);
}
__device__ __forceinline__ uint32_t smem_u32(const void* p) {
    uint32_t a;
    asm("{ .reg .u64 t; cvta.to.shared.u64 t, %1; cvt.u32.u64 %0, t; }" : "=r"(a) : "l"(p));
    return a;
}
__device__ __forceinline__ void ldmx4(uint32_t& r0, uint32_t& r1, uint32_t& r2, uint32_t& r3,
                                      uint32_t addr) {
    asm volatile("ldmatrix.sync.aligned.m8n8.x4.shared.b16 {%0,%1,%2,%3}, [%4];"
                 : "=r"(r0), "=r"(r1), "=r"(r2), "=r"(r3) : "r"(addr));
}
#define MMA16816(c, a0, a1, a2, a3, b0, b1)                                   \
    asm volatile("mma.sync.aligned.m16n8k16.row.col.f32.bf16.bf16.f32 "       \
                 "{%0,%1,%2,%3}, {%4,%5,%6,%7}, {%8,%9}, {%0,%1,%2,%3};"      \
                 : "+f"((c)[0]), "+f"((c)[1]), "+f"((c)[2]), "+f"((c)[3])     \
                 : "r"(a0), "r"(a1), "r"(a2), "r"(a3), "r"(b0), "r"(b1))

// ---------------- kernel 0: fused setup (zero + prep + switch) -------------------
// blocks [0,1024): zero g_acc/g_cnt; [1024,1040): weight prep; [1040,1104): switch
__global__ void setup_kernel(const float* __restrict__ Wk1, const float* __restrict__ Wk2,
                             const float* __restrict__ Wp0,
                             const float* __restrict__ qc,
                             const float* __restrict__ Wsw0, const float* __restrict__ bsw0,
                             const float* __restrict__ Wsw1, const float* __restrict__ bsw1) {
    const int bid = blockIdx.x, tid = threadIdx.x;
    if (bid < 1024) {
        const size_t n4 = (size_t)(2 * BB * N_QRY * CIN) / 4;
        float4* p = (float4*)g_acc;
        const float4 z = make_float4(0.f, 0.f, 0.f, 0.f);
        for (size_t i = (size_t)bid * 256 + tid; i < n4; i += (size_t)1024 * 256)
            p[i] = z;
        for (int i = bid * 256 + tid; i < 2 * N_QRY; i += 1024 * 256)
            g_cnt[i] = 0.f;
        return;
    }
    if (bid < 1040) {
        int i = (bid - 1024) * 256 + tid;     // 0..4095
        {
            int j = i & 63, k = i >> 6;
            uint32_t off = (uint32_t)(j * 128 + (((k >> 3) ^ (j & 7)) << 4) + (k & 7) * 2);
            float w1 = Wk1[i];
            __nv_bfloat16 h1 = __float2bfloat16_rn(w1);
            *(__nv_bfloat16*)(g_wt + 0     + off) = h1;
            *(__nv_bfloat16*)(g_wt + 8192  + off) = __float2bfloat16_rn(w1 - __bfloat162float(h1));
            float w2 = Wk2[i];
            __nv_bfloat16 h2 = __float2bfloat16_rn(w2);
            *(__nv_bfloat16*)(g_wt + 16384 + off) = h2;
            *(__nv_bfloat16*)(g_wt + 24576 + off) = __float2bfloat16_rn(w2 - __bfloat162float(h2));
        }
#pragma unroll
        for (int r = 0; r < 4; r++) {
            int ii = i + r * 4096;            // 0..16383 over Wp0
            int n = ii & 255, k = ii >> 8;
            float w = Wp0[k * 256 + n];
            __nv_bfloat16 h = __float2bfloat16_rn(w);
            uint32_t off = (uint32_t)(n * 128 + (((k >> 3) ^ (n & 7)) << 4) + (k & 7) * 2);
            *(__nv_bfloat16*)(g_wt2 + off) = h;
            *(__nv_bfloat16*)(g_wt2 + 32768 + off) = __float2bfloat16_rn(w - __bfloat162float(h));
        }
        return;
    }
    int q = (bid - 1040) * 256 + tid;
    if (q >= N_QRY) return;
    float x0 = qc[2 * q], x1 = qc[2 * q + 1];
    float l0 = bsw1[0], l1 = bsw1[1];
#pragma unroll
    for (int j = 0; j < 16; j++) {
        float hv = bsw0[j];
        hv = fmaf(x0, Wsw0[j], hv);
        hv = fmaf(x1, Wsw0[16 + j], hv);
        hv = fmaxf(hv, 0.f);
        l0 = fmaf(hv, Wsw1[2 * j], l0);
        l1 = fmaf(hv, Wsw1[2 * j + 1], l1);
    }
    float m = fmaxf(l0, l1);
    float e0 = expf(l0 - m), e1 = expf(l1 - m);
    float inv = 1.f / (e0 + e1);
    g_w[2 * q]     = e0 * inv;
    g_w[2 * q + 1] = e1 * inv;
}

// ---------------- shared GEMM core: acc += split-bf16(A[32wid..][64] @ W[64][64]^T)
__device__ __forceinline__ void mma_layer(uint32_t sbAH, uint32_t sbAL,
                                          uint32_t sbWH, uint32_t sbWL,
                                          int wid, int lane, float acc[2][8][4]) {
    const int r7   = lane & 7;
    const int arow = r7 + (((lane >> 3) & 1) << 3);
    const int asel = lane >> 4;
    const int brow = r7 + ((lane >> 4) << 3);
    const int bsel = (lane >> 3) & 1;
#pragma unroll
    for (int ks = 0; ks < 4; ks++) {
        uint32_t ah[2][4], al[2][4];
#pragma unroll
        for (int mi = 0; mi < 2; mi++) {
            uint32_t off = (uint32_t)((32 * wid + mi * 16 + arow) * 128 +
                                      (((ks * 2 + asel) ^ r7) << 4));
            ldmx4(ah[mi][0], ah[mi][1], ah[mi][2], ah[mi][3], sbAH + off);
            ldmx4(al[mi][0], al[mi][1], al[mi][2], al[mi][3], sbAL + off);
        }
#pragma unroll
        for (int p = 0; p < 4; p++) {
            uint32_t woff = (uint32_t)((p * 16 + brow) * 128 +
                                       (((ks * 2 + bsel) ^ r7) << 4));
            uint32_t bh0, bh1, bh2, bh3, bl0, bl1, bl2, bl3;
            ldmx4(bh0, bh1, bh2, bh3, sbWH + woff);
            ldmx4(bl0, bl1, bl2, bl3, sbWL + woff);
#pragma unroll
            for (int mi = 0; mi < 2; mi++) {
                MMA16816(acc[mi][2 * p],     ah[mi][0], ah[mi][1], ah[mi][2], ah[mi][3], bh0, bh1);
                MMA16816(acc[mi][2 * p],     al[mi][0], al[mi][1], al[mi][2], al[mi][3], bh0, bh1);
                MMA16816(acc[mi][2 * p],     ah[mi][0], ah[mi][1], ah[mi][2], ah[mi][3], bl0, bl1);
                MMA16816(acc[mi][2 * p + 1], ah[mi][0], ah[mi][1], ah[mi][2], ah[mi][3], bh2, bh3);
                MMA16816(acc[mi][2 * p + 1], al[mi][0], al[mi][1], al[mi][2], al[mi][3], bh2, bh3);
                MMA16816(acc[mi][2 * p + 1], ah[mi][0], ah[mi][1], ah[mi][2], ah[mi][3], bl2, bl3);
            }
        }
    }
}

// ---------------- kernel 2: HMMA edge MLP + segmented reduction (both scales) ----
#define EPB 128
#define X_IDX  0
#define X_W0T  1024
#define X_B0   2048
#define X_B1   2304
#define X_B2   2560
#define X_WT   2816
#define X_W1H  (X_WT + 0)
#define X_W1L  (X_WT + 8192)
#define X_W2H  (X_WT + 16384)
#define X_W2L  (X_WT + 24576)
#define X_AH   35584
#define X_AL   51968
#define X_K    2816
#define SMEM_EDGE_BYTES 68352

__global__ __launch_bounds__(128, 3) void edge_kernel(
    const float* __restrict__ latc, const float* __restrict__ qc,
    const float* __restrict__ rnd,
    const int* __restrict__ src0, const int* __restrict__ qry0,
    const int* __restrict__ src1, const int* __restrict__ qry1,
    const float* __restrict__ Wk0, const float* __restrict__ bk0,
    const float* __restrict__ bk1, const float* __restrict__ bk2,
    int nb0, int E0, int E1)
{
    extern __shared__ char smc[];
    float* smf = (float*)smc;
    const uint32_t sb = smem_u32(smc);
    const int tid = threadIdx.x, wid = tid >> 5, lane = tid & 31;

    int scale, tile, E;
    const int *src, *qry;
    if ((int)blockIdx.x < nb0) { scale = 0; tile = blockIdx.x; src = src0; qry = qry0; E = E0; }
    else { scale = 1; tile = blockIdx.x - nb0; src = src1; qry = qry1; E = E1; }

    {
        const uint4* gw = (const uint4*)g_wt;
        uint4* sw = (uint4*)(smc + X_WT);
#pragma unroll
        for (int i = 0; i < 16; i++) sw[tid + 128 * i] = gw[tid + 128 * i];
    }
    for (int i = tid; i < 256; i += 128) smf[(X_W0T >> 2) + (i & 63) * 4 + (i >> 6)] = Wk0[i];
    if (tid < 64) {
        smf[(X_B0 >> 2) + tid] = bk0[tid];
        smf[(X_B1 >> 2) + tid] = bk1[tid];
        smf[(X_B2 >> 2) + tid] = bk2[tid];
    }

    const int e = tile * EPB + tid;
    int s = 0, q = -1;
    if (e < E) { s = src[e]; q = qry[e]; }
    int* sidx = (int*)(smc + X_IDX);
    sidx[tid] = s;
    sidx[EPB + tid] = q;
    float f0 = latc[2 * s], f1 = latc[2 * s + 1];
    float f2 = 0.f, f3 = 0.f;
    if (q >= 0) { f2 = qc[2 * q]; f3 = qc[2 * q + 1]; }
    __syncthreads();

    // layer 1: 4 -> 64 per-thread, gelu, hi/lo split -> A tiles
    {
        const float4* w0 = (const float4*)(smc + X_W0T);
        const float* b0 = smf + (X_B0 >> 2);
#pragma unroll
        for (int c = 0; c < 8; c++) {
            float v[8];
#pragma unroll
            for (int jj = 0; jj < 8; jj++) {
                int j = c * 8 + jj;
                float4 w = w0[j];
                float a = b0[j];
                a = fmaf(f0, w.x, a); a = fmaf(f1, w.y, a);
                a = fmaf(f2, w.z, a); a = fmaf(f3, w.w, a);
                v[jj] = gelu_f(a);
            }
            uint32_t h[4], l[4];
#pragma unroll
            for (int m = 0; m < 4; m++) {
                h[m] = pkbf(v[2 * m], v[2 * m + 1]);
                float fx = __uint_as_float(h[m] << 16);
                float fy = __uint_as_float(h[m] & 0xFFFF0000u);
                l[m] = pkbf(v[2 * m] - fx, v[2 * m + 1] - fy);
            }
            uint32_t off = (uint32_t)(tid * 128 + ((c ^ (tid & 7)) << 4));
            *(uint4*)(smc + X_AH + off) = make_uint4(h[0], h[1], h[2], h[3]);
            *(uint4*)(smc + X_AL + off) = make_uint4(l[0], l[1], l[2], l[3]);
        }
    }
    __syncwarp();

    float acc[2][8][4];
#pragma unroll
    for (int mi = 0; mi < 2; mi++)
#pragma unroll
        for (int ni = 0; ni < 8; ni++)
#pragma unroll
            for (int z = 0; z < 4; z++) acc[mi][ni][z] = 0.f;

    mma_layer(sb + X_AH, sb + X_AL, sb + X_W1H, sb + X_W1L, wid, lane, acc);

    {
        const float* b1 = smf + (X_B1 >> 2);
        const int g = lane >> 2, t = lane & 3;
#pragma unroll
        for (int mi = 0; mi < 2; mi++) {
            int row0 = 32 * wid + mi * 16 + g;
#pragma unroll
            for (int ni = 0; ni < 8; ni++) {
                float2 bb = *(const float2*)(b1 + ni * 8 + t * 2);
                float v0 = gelu_f(acc[mi][ni][0] + bb.x);
                float v1 = gelu_f(acc[mi][ni][1] + bb.y);
                float v2 = gelu_f(acc[mi][ni][2] + bb.x);
                float v3 = gelu_f(acc[mi][ni][3] + bb.y);
                uint32_t h0 = pkbf(v0, v1);
                uint32_t l0 = pkbf(v0 - __uint_as_float(h0 << 16),
                                   v1 - __uint_as_float(h0 & 0xFFFF0000u));
                uint32_t h1 = pkbf(v2, v3);
                uint32_t l1 = pkbf(v2 - __uint_as_float(h1 << 16),
                                   v3 - __uint_as_float(h1 & 0xFFFF0000u));
                int r1 = row0 + 8;
                uint32_t offA = (uint32_t)(row0 * 128 + ((ni ^ (row0 & 7)) << 4) + t * 4);
                uint32_t offB = (uint32_t)(r1 * 128 + ((ni ^ (r1 & 7)) << 4) + t * 4);
                *(uint32_t*)(smc + X_AH + offA) = h0;
                *(uint32_t*)(smc + X_AL + offA) = l0;
                *(uint32_t*)(smc + X_AH + offB) = h1;
                *(uint32_t*)(smc + X_AL + offB) = l1;
                acc[mi][ni][0] = 0.f; acc[mi][ni][1] = 0.f;
                acc[mi][ni][2] = 0.f; acc[mi][ni][3] = 0.f;
            }
        }
    }
    __syncwarp();

    mma_layer(sb + X_AH, sb + X_AL, sb + X_W2H, sb + X_W2L, wid, lane, acc);
    __syncthreads();

    {
        const float* b2 = smf + (X_B2 >> 2);
        const int g = lane >> 2, t = lane & 3;
#pragma unroll
        for (int mi = 0; mi < 2; mi++) {
            int row0 = 32 * wid + mi * 16 + g;
#pragma unroll
            for (int ni = 0; ni < 8; ni++) {
                float2 bb = *(const float2*)(b2 + ni * 8 + t * 2);
                int colb = (ni * 8 + t * 2) * 4;
                *(float2*)(smc + X_K + row0 * 264 + colb) =
                    make_float2(acc[mi][ni][0] + bb.x, acc[mi][ni][1] + bb.y);
                *(float2*)(smc + X_K + (row0 + 8) * 264 + colb) =
                    make_float2(acc[mi][ni][2] + bb.x, acc[mi][ni][3] + bb.y);
            }
        }
    }
    __syncthreads();

    // phase B: segmented reduction, chunk-of-8 prefetch
    const int b  = wid;
    const int c2 = lane;
    const float* rb = rnd + (size_t)b * N_LAT * CIN + 2 * c2;
    float* accBase = g_acc + ((size_t)(scale * BB + b) * N_QRY) * CIN + 2 * c2;
    float* cntBase = g_cnt + scale * N_QRY;

    float ax = 0.f, ay = 0.f;
    int prevq = -1, run = 0;
#pragma unroll 1
    for (int base = 0; base < EPB; base += 8) {
        float2 rr[8], kk[8];
        int qv[8];
#pragma unroll
        for (int j = 0; j < 8; j++) {
            int ss = sidx[base + j];
            qv[j] = sidx[EPB + base + j];
            rr[j] = *(const float2*)(rb + (size_t)ss * CIN);
            kk[j] = *(const float2*)(smc + X_K + (base + j) * 264 + c2 * 8);
        }
#pragma unroll
        for (int j = 0; j < 8; j++) {
            int qq = qv[j];
            if (qq != prevq) {
                if (prevq >= 0) {
                    float* d = accBase + (size_t)prevq * CIN;
                    atomicAdd(d, ax);
                    atomicAdd(d + 1, ay);
                    if (tid == 0) atomicAdd(cntBase + prevq, (float)run);
                }
                ax = 0.f; ay = 0.f; run = 0; prevq = qq;
            }
            if (qq >= 0) {
                ax = fmaf(kk[j].x, rr[j].x, ax);
                ay = fmaf(kk[j].y, rr[j].y, ay);
                run++;
            }
        }
    }
    if (prevq >= 0) {
        float* d = accBase + (size_t)prevq * CIN;
        atomicAdd(d, ax);
        atomicAdd(d + 1, ay);
        if (tid == 0) atomicAdd(cntBase + prevq, (float)run);
    }
}

// ---------------- kernel 3: HMMA combine + projection MLP ------------------------
#define CM_WTH  0          // 32768 B Wp0^T hi
#define CM_WTL  32768      // 32768 B Wp0^T lo
#define CM_AH   65536      // 16384 B
#define CM_AL   81920      // 16384 B
#define CM_WP1  98304      // 4096 B (256 x float4)
#define CM_BP0  102400     // 1024 B
#define CM_BP1  103424     // 16 B
#define SMEM_COMB_BYTES 103440

__global__ __launch_bounds__(128) void combine_kernel(
    const float* __restrict__ bp0, const float* __restrict__ Wp1,
    const float* __restrict__ bp1, float* __restrict__ out)
{
    extern __shared__ char smc[];
    float* smf = (float*)smc;
    const uint32_t sb = smem_u32(smc);
    const int tid = threadIdx.x, wid = tid >> 5, lane = tid & 31;
    const int g = lane >> 2, t4 = lane & 3;

    {
        const uint4* gw = (const uint4*)g_wt2;
        uint4* sw = (uint4*)(smc + CM_WTH);
#pragma unroll
        for (int i = 0; i < 32; i++) sw[tid + 128 * i] = gw[tid + 128 * i];
    }
    for (int i = tid; i < 256; i += 128) ((uint4*)(smc + CM_WP1))[i] = ((const uint4*)Wp1)[i];
    if (tid < 64) ((uint4*)(smc + CM_BP0))[tid] = ((const uint4*)bp0)[tid];
    if (tid < 4) smf[(CM_BP1 >> 2) + tid] = bp1[tid];

    const int R = blockIdx.x * 128;
    {
        const size_t ss = (size_t)BB * N_QRY * CIN;
#pragma unroll 2
        for (int i = 0; i < 32; i++) {
            int lr = wid * 32 + i;
            int r = R + lr;
            int q = r & (N_QRY - 1);
            int b = r >> 14;
            float i0 = __fdividef(g_w[2 * q],     fmaxf(g_cnt[q], 1.f));
            float i1 = __fdividef(g_w[2 * q + 1], fmaxf(g_cnt[N_QRY + q], 1.f));
            size_t base0 = ((size_t)b * N_QRY + q) * CIN;
            size_t base1 = base0 + ss;
            float v  = fmaf(i0, g_acc[base0 + lane],      i1 * g_acc[base1 + lane]);
            float v2 = fmaf(i0, g_acc[base0 + lane + 32], i1 * g_acc[base1 + lane + 32]);
            __nv_bfloat16 h  = __float2bfloat16_rn(v);
            __nv_bfloat16 h2 = __float2bfloat16_rn(v2);
            uint32_t o1 = (uint32_t)(lr * 128 + (((lane >> 3) ^ (lr & 7)) << 4) + (lane & 7) * 2);
            uint32_t o2 = (uint32_t)(lr * 128 + ((((lane + 32) >> 3) ^ (lr & 7)) << 4) + (lane & 7) * 2);
            *(__nv_bfloat16*)(smc + CM_AH + o1) = h;
            *(__nv_bfloat16*)(smc + CM_AL + o1) = __float2bfloat16_rn(v - __bfloat162float(h));
            *(__nv_bfloat16*)(smc + CM_AH + o2) = h2;
            *(__nv_bfloat16*)(smc + CM_AL + o2) = __float2bfloat16_rn(v2 - __bfloat162float(h2));
        }
    }
    __syncthreads();

    float o_[4][4];
#pragma unroll
    for (int a = 0; a < 4; a++)
#pragma unroll
        for (int c = 0; c < 4; c++) o_[a][c] = 0.f;

    float acc[2][8][4];
    const float* bp0s = smf + (CM_BP0 >> 2);
    const float4* wp1s = (const float4*)(smc + CM_WP1);

#pragma unroll 1
    for (int c = 0; c < 4; c++) {
#pragma unroll
        for (int mi = 0; mi < 2; mi++)
#pragma unroll
            for (int ni = 0; ni < 8; ni++)
#pragma unroll
                for (int z = 0; z < 4; z++) acc[mi][ni][z] = 0.f;

        mma_layer(sb + CM_AH, sb + CM_AL,
                  sb + CM_WTH + c * 8192, sb + CM_WTL + c * 8192, wid, lane, acc);

#pragma unroll
        for (int ni = 0; ni < 8; ni++) {
            int col0 = c * 64 + ni * 8 + t4 * 2;
            float2 bb = *(const float2*)(bp0s + col0);
            float4 wA = wp1s[col0];
            float4 wB = wp1s[col0 + 1];
#pragma unroll
            for (int mi = 0; mi < 2; mi++) {
                float v0 = gelu_f(acc[mi][ni][0] + bb.x);
                float v1 = gelu_f(acc[mi][ni][1] + bb.y);
                float v2 = gelu_f(acc[mi][ni][2] + bb.x);
                float v3 = gelu_f(acc[mi][ni][3] + bb.y);
                float* oa = o_[mi * 2];
                oa[0] = fmaf(v0, wA.x, oa[0]); oa[1] = fmaf(v0, wA.y, oa[1]);
                oa[2] = fmaf(v0, wA.z, oa[2]); oa[3] = fmaf(v0, wA.w, oa[3]);
                oa[0] = fmaf(v1, wB.x, oa[0]); oa[1] = fmaf(v1, wB.y, oa[1]);
                oa[2] = fmaf(v1, wB.z, oa[2]); oa[3] = fmaf(v1, wB.w, oa[3]);
                float* ob = o_[mi * 2 + 1];
                ob[0] = fmaf(v2, wA.x, ob[0]); ob[1] = fmaf(v2, wA.y, ob[1]);
                ob[2] = fmaf(v2, wA.z, ob[2]); ob[3] = fmaf(v2, wA.w, ob[3]);
                ob[0] = fmaf(v3, wB.x, ob[0]); ob[1] = fmaf(v3, wB.y, ob[1]);
                ob[2] = fmaf(v3, wB.z, ob[2]); ob[3] = fmaf(v3, wB.w, ob[3]);
            }
        }
    }

#pragma unroll
    for (int rI = 0; rI < 4; rI++)
#pragma unroll
        for (int cc = 0; cc < 4; cc++) {
            float v = o_[rI][cc];
            v += __shfl_xor_sync(0xffffffffu, v, 1);
            v += __shfl_xor_sync(0xffffffffu, v, 2);
            o_[rI][cc] = v;
        }
    if (t4 == 0) {
        const float* b1 = smf + (CM_BP1 >> 2);
#pragma unroll
        for (int rI = 0; rI < 4; rI++) {
            int row = R + 32 * wid + g + (rI >> 1) * 16 + (rI & 1) * 8;
            float4 r4;
            r4.x = o_[rI][0] + b1[0];
            r4.y = o_[rI][1] + b1[1];
            r4.z = o_[rI][2] + b1[2];
            r4.w = o_[rI][3] + b1[3];
            ((float4*)out)[row] = r4;
        }
    }
}

// ---------------- launch ---------------------------------------------------------
extern "C" void kernel_launch(void* const* d_in, const int* in_sizes, int n_in,
                              void* d_out, int out_size)
{
    const float* latc = (const float*)d_in[0];
    const float* rnd  = (const float*)d_in[1];
    const float* qc   = (const float*)d_in[2];
    const int*   src0 = (const int*)d_in[3];
    const int*   qry0 = (const int*)d_in[4];
    const int*   src1 = (const int*)d_in[5];
    const int*   qry1 = (const int*)d_in[6];
    const float* Wk0  = (const float*)d_in[7];
    const float* bk0  = (const float*)d_in[8];
    const float* Wk1  = (const float*)d_in[9];
    const float* bk1  = (const float*)d_in[10];
    const float* Wk2  = (const float*)d_in[11];
    const float* bk2  = (const float*)d_in[12];
    const float* Wsw0 = (const float*)d_in[13];
    const float* bsw0 = (const float*)d_in[14];
    const float* Wsw1 = (const float*)d_in[15];
    const float* bsw1 = (const float*)d_in[16];
    const float* Wp0  = (const float*)d_in[17];
    const float* bp0  = (const float*)d_in[18];
    const float* Wp1  = (const float*)d_in[19];
    const float* bp1  = (const float*)d_in[20];

    const int E0 = in_sizes[3];
    const int E1 = in_sizes[5];
    const int nb0 = (E0 + EPB - 1) / EPB;
    const int nb1 = (E1 + EPB - 1) / EPB;

    cudaFuncSetAttribute(edge_kernel,    cudaFuncAttributeMaxDynamicSharedMemorySize, SMEM_EDGE_BYTES);
    cudaFuncSetAttribute(combine_kernel, cudaFuncAttributeMaxDynamicSharedMemorySize, SMEM_COMB_BYTES);

    setup_kernel<<<1104, 256>>>(Wk1, Wk2, Wp0, qc, Wsw0, bsw0, Wsw1, bsw1);
    edge_kernel<<<nb0 + nb1, 128, SMEM_EDGE_BYTES>>>(latc, qc, rnd,
                                                     src0, qry0, src1, qry1,
                                                     Wk0, bk0, bk1, bk2, nb0, E0, E1);
    combine_kernel<<<512, 128, SMEM_COMB_BYTES>>>(bp0, Wp1, bp1, (float*)d_out);
}

// round 16
// speedup vs baseline: 5.3339x; 1.1379x over previous
#include <cuda_runtime.h>
#include <cuda_fp16.h>
#include <cstdint>

#define N_LAT 4096
#define N_QRY 16384
#define BB    4
#define CIN   64

// ---------------- scratch (device globals: allocation-free rule) ----------------
__device__ float g_acc[2 * BB * N_QRY * CIN];   // [scale][b][q][c], 33.5 MB
__device__ float g_cnt[2 * N_QRY];              // edge counts per query per scale
__device__ float g_w[N_QRY * 2];                // softmax switch weights
__device__ unsigned char g_wt[16384];           // W1H | W2H swizzled fp16 tiles
__device__ unsigned char g_wt2[32768];          // Wp0^T fp16 swizzled

// ---------------- helpers --------------------------------------------------------
__device__ __forceinline__ uint32_t pkhf(float a, float b) {
    __half2 t = __floats2half2_rn(a, b);
    return *reinterpret_cast<uint32_t*>(&t);
}
__device__ __forceinline__ float2 hf2f(uint32_t u) {
    __half2 h = *reinterpret_cast<__half2*>(&u);
    return __half22float2(h);
}
// fast gelu: MUFU.TANH (1 MUFU, ~5 FMA)
__device__ __forceinline__ float gelu_f(float x) {
    float y = 0.7978845608028654f * fmaf(0.044715f, x * x, 1.0f) * x;
    float t;
    asm("tanh.approx.f32 %0, %1;" : "=f"(t) : "f"(y));
    float h = 0.5f * x;
    return fmaf(h, t, h);
}
__device__ __forceinline__ uint32_t smem_u32(const void* p) {
    uint32_t a;
    asm("{ .reg .u64 t; cvta.to.shared.u64 t, %1; cvt.u32.u64 %0, t; }" : "=r"(a) : "l"(p));
    return a;
}
__device__ __forceinline__ void ldmx4(uint32_t& r0, uint32_t& r1, uint32_t& r2, uint32_t& r3,
                                      uint32_t addr) {
    asm volatile("ldmatrix.sync.aligned.m8n8.x4.shared.b16 {%0,%1,%2,%3}, [%4];"
                 : "=r"(r0), "=r"(r1), "=r"(r2), "=r"(r3) : "r"(addr));
}
#define MMA16816(c, a0, a1, a2, a3, b0, b1)                                   \
    asm volatile("mma.sync.aligned.m16n8k16.row.col.f32.f16.f16.f32 "         \
                 "{%0,%1,%2,%3}, {%4,%5,%6,%7}, {%8,%9}, {%0,%1,%2,%3};"      \
                 : "+f"((c)[0]), "+f"((c)[1]), "+f"((c)[2]), "+f"((c)[3])     \
                 : "r"(a0), "r"(a1), "r"(a2), "r"(a3), "r"(b0), "r"(b1))

// ---------------- kernel 0: fused setup (zero + prep + switch) -------------------
__global__ void setup_kernel(const float* __restrict__ Wk1, const float* __restrict__ Wk2,
                             const float* __restrict__ Wp0,
                             const float* __restrict__ qc,
                             const float* __restrict__ Wsw0, const float* __restrict__ bsw0,
                             const float* __restrict__ Wsw1, const float* __restrict__ bsw1) {
    const int bid = blockIdx.x, tid = threadIdx.x;
    if (bid < 1024) {
        const size_t n4 = (size_t)(2 * BB * N_QRY * CIN) / 4;
        float4* p = (float4*)g_acc;
        const float4 z = make_float4(0.f, 0.f, 0.f, 0.f);
        for (size_t i = (size_t)bid * 256 + tid; i < n4; i += (size_t)1024 * 256)
            p[i] = z;
        for (int i = bid * 256 + tid; i < 2 * N_QRY; i += 1024 * 256)
            g_cnt[i] = 0.f;
        return;
    }
    if (bid < 1040) {
        int i = (bid - 1024) * 256 + tid;     // 0..4095
        {
            int j = i & 63, k = i >> 6;
            uint32_t off = (uint32_t)(j * 128 + (((k >> 3) ^ (j & 7)) << 4) + (k & 7) * 2);
            *(__half*)(g_wt + 0    + off) = __float2half_rn(Wk1[i]);
            *(__half*)(g_wt + 8192 + off) = __float2half_rn(Wk2[i]);
        }
#pragma unroll
        for (int r = 0; r < 4; r++) {
            int ii = i + r * 4096;            // 0..16383 over Wp0
            int n = ii & 255, k = ii >> 8;
            uint32_t off = (uint32_t)(n * 128 + (((k >> 3) ^ (n & 7)) << 4) + (k & 7) * 2);
            *(__half*)(g_wt2 + off) = __float2half_rn(Wp0[k * 256 + n]);
        }
        return;
    }
    int q = (bid - 1040) * 256 + tid;
    if (q >= N_QRY) return;
    float x0 = qc[2 * q], x1 = qc[2 * q + 1];
    float l0 = bsw1[0], l1 = bsw1[1];
#pragma unroll
    for (int j = 0; j < 16; j++) {
        float hv = bsw0[j];
        hv = fmaf(x0, Wsw0[j], hv);
        hv = fmaf(x1, Wsw0[16 + j], hv);
        hv = fmaxf(hv, 0.f);
        l0 = fmaf(hv, Wsw1[2 * j], l0);
        l1 = fmaf(hv, Wsw1[2 * j + 1], l1);
    }
    float m = fmaxf(l0, l1);
    float e0 = expf(l0 - m), e1 = expf(l1 - m);
    float inv = 1.f / (e0 + e1);
    g_w[2 * q]     = e0 * inv;
    g_w[2 * q + 1] = e1 * inv;
}

// ---- 2-term GEMM core: acc += (Ahi + Alo)[32wid..][64] @ W[64][64]^T (W fp16) ---
__device__ __forceinline__ void mma_layer(uint32_t sbAH, uint32_t sbAL, uint32_t sbWH,
                                          int wid, int lane, float acc[2][8][4]) {
    const int r7   = lane & 7;
    const int arow = r7 + (((lane >> 3) & 1) << 3);
    const int asel = lane >> 4;
    const int brow = r7 + ((lane >> 4) << 3);
    const int bsel = (lane >> 3) & 1;
#pragma unroll
    for (int ks = 0; ks < 4; ks++) {
        uint32_t ah[2][4], al[2][4];
#pragma unroll
        for (int mi = 0; mi < 2; mi++) {
            uint32_t off = (uint32_t)((32 * wid + mi * 16 + arow) * 128 +
                                      (((ks * 2 + asel) ^ r7) << 4));
            ldmx4(ah[mi][0], ah[mi][1], ah[mi][2], ah[mi][3], sbAH + off);
            ldmx4(al[mi][0], al[mi][1], al[mi][2], al[mi][3], sbAL + off);
        }
#pragma unroll
        for (int p = 0; p < 4; p++) {
            uint32_t woff = (uint32_t)((p * 16 + brow) * 128 +
                                       (((ks * 2 + bsel) ^ r7) << 4));
            uint32_t bh0, bh1, bh2, bh3;
            ldmx4(bh0, bh1, bh2, bh3, sbWH + woff);
#pragma unroll
            for (int mi = 0; mi < 2; mi++) {
                MMA16816(acc[mi][2 * p],     ah[mi][0], ah[mi][1], ah[mi][2], ah[mi][3], bh0, bh1);
                MMA16816(acc[mi][2 * p],     al[mi][0], al[mi][1], al[mi][2], al[mi][3], bh0, bh1);
                MMA16816(acc[mi][2 * p + 1], ah[mi][0], ah[mi][1], ah[mi][2], ah[mi][3], bh2, bh3);
                MMA16816(acc[mi][2 * p + 1], al[mi][0], al[mi][1], al[mi][2], al[mi][3], bh2, bh3);
            }
        }
    }
}

// ---------------- kernel 2: HMMA edge MLP + segmented reduction (both scales) ----
#define EPB 128
#define X_IDX  0
#define X_W0T  1024
#define X_B0   2048
#define X_B1   2304
#define X_B2   2560
#define X_WT   2816
#define X_W1H  (X_WT + 0)
#define X_W2H  (X_WT + 8192)
#define X_AH   19200
#define X_AL   35584
#define X_K    2816
#define SMEM_EDGE_BYTES 51968

__global__ __launch_bounds__(128, 3) void edge_kernel(
    const float* __restrict__ latc, const float* __restrict__ qc,
    const float* __restrict__ rnd,
    const int* __restrict__ src0, const int* __restrict__ qry0,
    const int* __restrict__ src1, const int* __restrict__ qry1,
    const float* __restrict__ Wk0, const float* __restrict__ bk0,
    const float* __restrict__ bk1, const float* __restrict__ bk2,
    int nb0, int E0, int E1)
{
    extern __shared__ char smc[];
    float* smf = (float*)smc;
    const uint32_t sb = smem_u32(smc);
    const int tid = threadIdx.x, wid = tid >> 5, lane = tid & 31;

    int scale, tile, E;
    const int *src, *qry;
    if ((int)blockIdx.x < nb0) { scale = 0; tile = blockIdx.x; src = src0; qry = qry0; E = E0; }
    else { scale = 1; tile = blockIdx.x - nb0; src = src1; qry = qry1; E = E1; }

    {
        const uint4* gw = (const uint4*)g_wt;
        uint4* sw = (uint4*)(smc + X_WT);
#pragma unroll
        for (int i = 0; i < 8; i++) sw[tid + 128 * i] = gw[tid + 128 * i];
    }
    for (int i = tid; i < 256; i += 128) smf[(X_W0T >> 2) + (i & 63) * 4 + (i >> 6)] = Wk0[i];
    if (tid < 64) {
        smf[(X_B0 >> 2) + tid] = bk0[tid];
        smf[(X_B1 >> 2) + tid] = bk1[tid];
        smf[(X_B2 >> 2) + tid] = bk2[tid];
    }

    const int e = tile * EPB + tid;
    int s = 0, q = -1;
    if (e < E) { s = src[e]; q = qry[e]; }
    int* sidx = (int*)(smc + X_IDX);
    sidx[tid] = s;
    sidx[EPB + tid] = q;
    float f0 = latc[2 * s], f1 = latc[2 * s + 1];
    float f2 = 0.f, f3 = 0.f;
    if (q >= 0) { f2 = qc[2 * q]; f3 = qc[2 * q + 1]; }
    __syncthreads();

    // layer 1: 4 -> 64 per-thread, gelu, fp16 hi/lo split -> A tiles
    {
        const float4* w0 = (const float4*)(smc + X_W0T);
        const float* b0 = smf + (X_B0 >> 2);
#pragma unroll
        for (int c = 0; c < 8; c++) {
            float v[8];
#pragma unroll
            for (int jj = 0; jj < 8; jj++) {
                int j = c * 8 + jj;
                float4 w = w0[j];
                float a = b0[j];
                a = fmaf(f0, w.x, a); a = fmaf(f1, w.y, a);
                a = fmaf(f2, w.z, a); a = fmaf(f3, w.w, a);
                v[jj] = gelu_f(a);
            }
            uint32_t h[4], l[4];
#pragma unroll
            for (int m = 0; m < 4; m++) {
                h[m] = pkhf(v[2 * m], v[2 * m + 1]);
                float2 hv = hf2f(h[m]);
                l[m] = pkhf(v[2 * m] - hv.x, v[2 * m + 1] - hv.y);
            }
            uint32_t off = (uint32_t)(tid * 128 + ((c ^ (tid & 7)) << 4));
            *(uint4*)(smc + X_AH + off) = make_uint4(h[0], h[1], h[2], h[3]);
            *(uint4*)(smc + X_AL + off) = make_uint4(l[0], l[1], l[2], l[3]);
        }
    }
    __syncwarp();

    float acc[2][8][4];
#pragma unroll
    for (int mi = 0; mi < 2; mi++)
#pragma unroll
        for (int ni = 0; ni < 8; ni++)
#pragma unroll
            for (int z = 0; z < 4; z++) acc[mi][ni][z] = 0.f;

    mma_layer(sb + X_AH, sb + X_AL, sb + X_W1H, wid, lane, acc);

    {
        const float* b1 = smf + (X_B1 >> 2);
        const int g = lane >> 2, t = lane & 3;
#pragma unroll
        for (int mi = 0; mi < 2; mi++) {
            int row0 = 32 * wid + mi * 16 + g;
#pragma unroll
            for (int ni = 0; ni < 8; ni++) {
                float2 bb = *(const float2*)(b1 + ni * 8 + t * 2);
                float v0 = gelu_f(acc[mi][ni][0] + bb.x);
                float v1 = gelu_f(acc[mi][ni][1] + bb.y);
                float v2 = gelu_f(acc[mi][ni][2] + bb.x);
                float v3 = gelu_f(acc[mi][ni][3] + bb.y);
                uint32_t h0 = pkhf(v0, v1);
                float2 hv0 = hf2f(h0);
                uint32_t l0 = pkhf(v0 - hv0.x, v1 - hv0.y);
                uint32_t h1 = pkhf(v2, v3);
                float2 hv1 = hf2f(h1);
                uint32_t l1 = pkhf(v2 - hv1.x, v3 - hv1.y);
                int r1 = row0 + 8;
                uint32_t offA = (uint32_t)(row0 * 128 + ((ni ^ (row0 & 7)) << 4) + t * 4);
                uint32_t offB = (uint32_t)(r1 * 128 + ((ni ^ (r1 & 7)) << 4) + t * 4);
                *(uint32_t*)(smc + X_AH + offA) = h0;
                *(uint32_t*)(smc + X_AL + offA) = l0;
                *(uint32_t*)(smc + X_AH + offB) = h1;
                *(uint32_t*)(smc + X_AL + offB) = l1;
                acc[mi][ni][0] = 0.f; acc[mi][ni][1] = 0.f;
                acc[mi][ni][2] = 0.f; acc[mi][ni][3] = 0.f;
            }
        }
    }
    __syncwarp();

    mma_layer(sb + X_AH, sb + X_AL, sb + X_W2H, wid, lane, acc);
    __syncthreads();   // WT/A regions now dead; K buffer overlays them

    {
        const float* b2 = smf + (X_B2 >> 2);
        const int g = lane >> 2, t = lane & 3;
#pragma unroll
        for (int mi = 0; mi < 2; mi++) {
            int row0 = 32 * wid + mi * 16 + g;
#pragma unroll
            for (int ni = 0; ni < 8; ni++) {
                float2 bb = *(const float2*)(b2 + ni * 8 + t * 2);
                int colb = (ni * 8 + t * 2) * 4;
                *(float2*)(smc + X_K + row0 * 264 + colb) =
                    make_float2(acc[mi][ni][0] + bb.x, acc[mi][ni][1] + bb.y);
                *(float2*)(smc + X_K + (row0 + 8) * 264 + colb) =
                    make_float2(acc[mi][ni][2] + bb.x, acc[mi][ni][3] + bb.y);
            }
        }
    }
    __syncthreads();

    // phase B: segmented reduction, chunk-of-8 prefetch
    const int b  = wid;
    const int c2 = lane;
    const float* rb = rnd + (size_t)b * N_LAT * CIN + 2 * c2;
    float* accBase = g_acc + ((size_t)(scale * BB + b) * N_QRY) * CIN + 2 * c2;
    float* cntBase = g_cnt + scale * N_QRY;

    float ax = 0.f, ay = 0.f;
    int prevq = -1, run = 0;
#pragma unroll 1
    for (int base = 0; base < EPB; base += 8) {
        float2 rr[8], kk[8];
        int qv[8];
#pragma unroll
        for (int j = 0; j < 8; j++) {
            int ss = sidx[base + j];
            qv[j] = sidx[EPB + base + j];
            rr[j] = *(const float2*)(rb + (size_t)ss * CIN);
            kk[j] = *(const float2*)(smc + X_K + (base + j) * 264 + c2 * 8);
        }
#pragma unroll
        for (int j = 0; j < 8; j++) {
            int qq = qv[j];
            if (qq != prevq) {
                if (prevq >= 0) {
                    float* d = accBase + (size_t)prevq * CIN;
                    atomicAdd(d, ax);
                    atomicAdd(d + 1, ay);
                    if (tid == 0) atomicAdd(cntBase + prevq, (float)run);
                }
                ax = 0.f; ay = 0.f; run = 0; prevq = qq;
            }
            if (qq >= 0) {
                ax = fmaf(kk[j].x, rr[j].x, ax);
                ay = fmaf(kk[j].y, rr[j].y, ay);
                run++;
            }
        }
    }
    if (prevq >= 0) {
        float* d = accBase + (size_t)prevq * CIN;
        atomicAdd(d, ax);
        atomicAdd(d + 1, ay);
        if (tid == 0) atomicAdd(cntBase + prevq, (float)run);
    }
}

// ---------------- kernel 3: HMMA combine + projection MLP ------------------------
#define CM_WTH  0          // 32768 B Wp0^T fp16
#define CM_AH   32768      // 16384 B
#define CM_AL   49152      // 16384 B
#define CM_WP1  65536      // 4096 B (256 x float4)
#define CM_BP0  69632      // 1024 B
#define CM_BP1  70656      // 16 B
#define SMEM_COMB_BYTES 70672

__global__ __launch_bounds__(128) void combine_kernel(
    const float* __restrict__ bp0, const float* __restrict__ Wp1,
    const float* __restrict__ bp1, float* __restrict__ out)
{
    extern __shared__ char smc[];
    float* smf = (float*)smc;
    const uint32_t sb = smem_u32(smc);
    const int tid = threadIdx.x, wid = tid >> 5, lane = tid & 31;
    const int g = lane >> 2, t4 = lane & 3;

    {
        const uint4* gw = (const uint4*)g_wt2;
        uint4* sw = (uint4*)(smc + CM_WTH);
#pragma unroll
        for (int i = 0; i < 16; i++) sw[tid + 128 * i] = gw[tid + 128 * i];
    }
    for (int i = tid; i < 256; i += 128) ((uint4*)(smc + CM_WP1))[i] = ((const uint4*)Wp1)[i];
    if (tid < 64) ((uint4*)(smc + CM_BP0))[tid] = ((const uint4*)bp0)[tid];
    if (tid < 4) smf[(CM_BP1 >> 2) + tid] = bp1[tid];

    const int R = blockIdx.x * 128;
    {
        const size_t ss = (size_t)BB * N_QRY * CIN;
#pragma unroll 2
        for (int i = 0; i < 32; i++) {
            int lr = wid * 32 + i;
            int r = R + lr;
            int q = r & (N_QRY - 1);
            int b = r >> 14;
            float i0 = __fdividef(g_w[2 * q],     fmaxf(g_cnt[q], 1.f));
            float i1 = __fdividef(g_w[2 * q + 1], fmaxf(g_cnt[N_QRY + q], 1.f));
            size_t base0 = ((size_t)b * N_QRY + q) * CIN;
            size_t base1 = base0 + ss;
            float v  = fmaf(i0, g_acc[base0 + lane],      i1 * g_acc[base1 + lane]);
            float v2 = fmaf(i0, g_acc[base0 + lane + 32], i1 * g_acc[base1 + lane + 32]);
            __half h  = __float2half_rn(v);
            __half h2 = __float2half_rn(v2);
            uint32_t o1 = (uint32_t)(lr * 128 + (((lane >> 3) ^ (lr & 7)) << 4) + (lane & 7) * 2);
            uint32_t o2 = (uint32_t)(lr * 128 + ((((lane + 32) >> 3) ^ (lr & 7)) << 4) + (lane & 7) * 2);
            *(__half*)(smc + CM_AH + o1) = h;
            *(__half*)(smc + CM_AL + o1) = __float2half_rn(v - __half2float(h));
            *(__half*)(smc + CM_AH + o2) = h2;
            *(__half*)(smc + CM_AL + o2) = __float2half_rn(v2 - __half2float(h2));
        }
    }
    __syncthreads();

    float o_[4][4];
#pragma unroll
    for (int a = 0; a < 4; a++)
#pragma unroll
        for (int c = 0; c < 4; c++) o_[a][c] = 0.f;

    float acc[2][8][4];
    const float* bp0s = smf + (CM_BP0 >> 2);
    const float4* wp1s = (const float4*)(smc + CM_WP1);

#pragma unroll 1
    for (int c = 0; c < 4; c++) {
#pragma unroll
        for (int mi = 0; mi < 2; mi++)
#pragma unroll
            for (int ni = 0; ni < 8; ni++)
#pragma unroll
                for (int z = 0; z < 4; z++) acc[mi][ni][z] = 0.f;

        mma_layer(sb + CM_AH, sb + CM_AL, sb + CM_WTH + c * 8192, wid, lane, acc);

#pragma unroll
        for (int ni = 0; ni < 8; ni++) {
            int col0 = c * 64 + ni * 8 + t4 * 2;
            float2 bb = *(const float2*)(bp0s + col0);
            float4 wA = wp1s[col0];
            float4 wB = wp1s[col0 + 1];
#pragma unroll
            for (int mi = 0; mi < 2; mi++) {
                float v0 = gelu_f(acc[mi][ni][0] + bb.x);
                float v1 = gelu_f(acc[mi][ni][1] + bb.y);
                float v2 = gelu_f(acc[mi][ni][2] + bb.x);
                float v3 = gelu_f(acc[mi][ni][3] + bb.y);
                float* oa = o_[mi * 2];
                oa[0] = fmaf(v0, wA.x, oa[0]); oa[1] = fmaf(v0, wA.y, oa[1]);
                oa[2] = fmaf(v0, wA.z, oa[2]); oa[3] = fmaf(v0, wA.w, oa[3]);
                oa[0] = fmaf(v1, wB.x, oa[0]); oa[1] = fmaf(v1, wB.y, oa[1]);
                oa[2] = fmaf(v1, wB.z, oa[2]); oa[3] = fmaf(v1, wB.w, oa[3]);
                float* ob = o_[mi * 2 + 1];
                ob[0] = fmaf(v2, wA.x, ob[0]); ob[1] = fmaf(v2, wA.y, ob[1]);
                ob[2] = fmaf(v2, wA.z, ob[2]); ob[3] = fmaf(v2, wA.w, ob[3]);
                ob[0] = fmaf(v3, wB.x, ob[0]); ob[1] = fmaf(v3, wB.y, ob[1]);
                ob[2] = fmaf(v3, wB.z, ob[2]); ob[3] = fmaf(v3, wB.w, ob[3]);
            }
        }
    }

#pragma unroll
    for (int rI = 0; rI < 4; rI++)
#pragma unroll
        for (int cc = 0; cc < 4; cc++) {
            float v = o_[rI][cc];
            v += __shfl_xor_sync(0xffffffffu, v, 1);
            v += __shfl_xor_sync(0xffffffffu, v, 2);
            o_[rI][cc] = v;
        }
    if (t4 == 0) {
        const float* b1 = smf + (CM_BP1 >> 2);
#pragma unroll
        for (int rI = 0; rI < 4; rI++) {
            int row = R + 32 * wid + g + (rI >> 1) * 16 + (rI & 1) * 8;
            float4 r4;
            r4.x = o_[rI][0] + b1[0];
            r4.y = o_[rI][1] + b1[1];
            r4.z = o_[rI][2] + b1[2];
            r4.w = o_[rI][3] + b1[3];
            ((float4*)out)[row] = r4;
        }
    }
}

// ---------------- launch ---------------------------------------------------------
extern "C" void kernel_launch(void* const* d_in, const int* in_sizes, int n_in,
                              void* d_out, int out_size)
{
    const float* latc = (const float*)d_in[0];
    const float* rnd  = (const float*)d_in[1];
    const float* qc   = (const float*)d_in[2];
    const int*   src0 = (const int*)d_in[3];
    const int*   qry0 = (const int*)d_in[4];
    const int*   src1 = (const int*)d_in[5];
    const int*   qry1 = (const int*)d_in[6];
    const float* Wk0  = (const float*)d_in[7];
    const float* bk0  = (const float*)d_in[8];
    const float* Wk1  = (const float*)d_in[9];
    const float* bk1  = (const float*)d_in[10];
    const float* Wk2  = (const float*)d_in[11];
    const float* bk2  = (const float*)d_in[12];
    const float* Wsw0 = (const float*)d_in[13];
    const float* bsw0 = (const float*)d_in[14];
    const float* Wsw1 = (const float*)d_in[15];
    const float* bsw1 = (const float*)d_in[16];
    const float* Wp0  = (const float*)d_in[17];
    const float* bp0  = (const float*)d_in[18];
    const float* Wp1  = (const float*)d_in[19];
    const float* bp1  = (const float*)d_in[20];

    const int E0 = in_sizes[3];
    const int E1 = in_sizes[5];
    const int nb0 = (E0 + EPB - 1) / EPB;
    const int nb1 = (E1 + EPB - 1) / EPB;

    cudaFuncSetAttribute(edge_kernel,    cudaFuncAttributeMaxDynamicSharedMemorySize, SMEM_EDGE_BYTES);
    cudaFuncSetAttribute(combine_kernel, cudaFuncAttributeMaxDynamicSharedMemorySize, SMEM_COMB_BYTES);

    setup_kernel<<<1104, 256>>>(Wk1, Wk2, Wp0, qc, Wsw0, bsw0, Wsw1, bsw1);
    edge_kernel<<<nb0 + nb1, 128, SMEM_EDGE_BYTES>>>(latc, qc, rnd,
                                                     src0, qry0, src1, qry1,
                                                     Wk0, bk0, bk1, bk2, nb0, E0, E1);
    combine_kernel<<<512, 128, SMEM_COMB_BYTES>>>(bp0, Wp1, bp1, (float*)d_out);
}

// round 17
// speedup vs baseline: 6.6941x; 1.2550x over previous
#include <cuda_runtime.h>
#include <cuda_fp16.h>
#include <cstdint>

#define N_LAT 4096
#define N_QRY 16384
#define BB    4
#define CIN   64

// ---------------- scratch (device globals: allocation-free rule) ----------------
__device__ float g_acc[2 * BB * N_QRY * CIN];   // [scale][b][q][c], 33.5 MB
__device__ float g_cnt[2 * N_QRY];              // edge counts per query per scale
__device__ float g_w[N_QRY * 2];                // softmax switch weights
__device__ unsigned char g_wt[16384];           // W1H | W2H swizzled fp16 tiles
__device__ unsigned char g_wt2[32768];          // Wp0^T fp16 swizzled

// ---------------- helpers --------------------------------------------------------
__device__ __forceinline__ uint32_t pkhf(float a, float b) {
    __half2 t = __floats2half2_rn(a, b);
    return *reinterpret_cast<uint32_t*>(&t);
}
// fast gelu: MUFU.TANH (1 MUFU, ~5 FMA)
__device__ __forceinline__ float gelu_f(float x) {
    float y = 0.7978845608028654f * fmaf(0.044715f, x * x, 1.0f) * x;
    float t;
    asm("tanh.approx.f32 %0, %1;" : "=f"(t) : "f"(y));
    float h = 0.5f * x;
    return fmaf(h, t, h);
}
__device__ __forceinline__ uint32_t smem_u32(const void* p) {
    uint32_t a;
    asm("{ .reg .u64 t; cvta.to.shared.u64 t, %1; cvt.u32.u64 %0, t; }" : "=r"(a) : "l"(p));
    return a;
}
__device__ __forceinline__ void ldmx4(uint32_t& r0, uint32_t& r1, uint32_t& r2, uint32_t& r3,
                                      uint32_t addr) {
    asm volatile("ldmatrix.sync.aligned.m8n8.x4.shared.b16 {%0,%1,%2,%3}, [%4];"
                 : "=r"(r0), "=r"(r1), "=r"(r2), "=r"(r3) : "r"(addr));
}
#define MMA16816(c, a0, a1, a2, a3, b0, b1)                                   \
    asm volatile("mma.sync.aligned.m16n8k16.row.col.f32.f16.f16.f32 "         \
                 "{%0,%1,%2,%3}, {%4,%5,%6,%7}, {%8,%9}, {%0,%1,%2,%3};"      \
                 : "+f"((c)[0]), "+f"((c)[1]), "+f"((c)[2]), "+f"((c)[3])     \
                 : "r"(a0), "r"(a1), "r"(a2), "r"(a3), "r"(b0), "r"(b1))

// ---------------- kernel 0: fused setup (zero + prep + switch) -------------------
__global__ void setup_kernel(const float* __restrict__ Wk1, const float* __restrict__ Wk2,
                             const float* __restrict__ Wp0,
                             const float* __restrict__ qc,
                             const float* __restrict__ Wsw0, const float* __restrict__ bsw0,
                             const float* __restrict__ Wsw1, const float* __restrict__ bsw1) {
    const int bid = blockIdx.x, tid = threadIdx.x;
    if (bid < 1024) {
        const size_t n4 = (size_t)(2 * BB * N_QRY * CIN) / 4;
        float4* p = (float4*)g_acc;
        const float4 z = make_float4(0.f, 0.f, 0.f, 0.f);
        for (size_t i = (size_t)bid * 256 + tid; i < n4; i += (size_t)1024 * 256)
            p[i] = z;
        for (int i = bid * 256 + tid; i < 2 * N_QRY; i += 1024 * 256)
            g_cnt[i] = 0.f;
        return;
    }
    if (bid < 1040) {
        int i = (bid - 1024) * 256 + tid;     // 0..4095
        {
            int j = i & 63, k = i >> 6;
            uint32_t off = (uint32_t)(j * 128 + (((k >> 3) ^ (j & 7)) << 4) + (k & 7) * 2);
            *(__half*)(g_wt + 0    + off) = __float2half_rn(Wk1[i]);
            *(__half*)(g_wt + 8192 + off) = __float2half_rn(Wk2[i]);
        }
#pragma unroll
        for (int r = 0; r < 4; r++) {
            int ii = i + r * 4096;            // 0..16383 over Wp0
            int n = ii & 255, k = ii >> 8;
            uint32_t off = (uint32_t)(n * 128 + (((k >> 3) ^ (n & 7)) << 4) + (k & 7) * 2);
            *(__half*)(g_wt2 + off) = __float2half_rn(Wp0[k * 256 + n]);
        }
        return;
    }
    int q = (bid - 1040) * 256 + tid;
    if (q >= N_QRY) return;
    float x0 = qc[2 * q], x1 = qc[2 * q + 1];
    float l0 = bsw1[0], l1 = bsw1[1];
#pragma unroll
    for (int j = 0; j < 16; j++) {
        float hv = bsw0[j];
        hv = fmaf(x0, Wsw0[j], hv);
        hv = fmaf(x1, Wsw0[16 + j], hv);
        hv = fmaxf(hv, 0.f);
        l0 = fmaf(hv, Wsw1[2 * j], l0);
        l1 = fmaf(hv, Wsw1[2 * j + 1], l1);
    }
    float m = fmaxf(l0, l1);
    float e0 = expf(l0 - m), e1 = expf(l1 - m);
    float inv = 1.f / (e0 + e1);
    g_w[2 * q]     = e0 * inv;
    g_w[2 * q + 1] = e1 * inv;
}

// ---- 1-term GEMM core: acc += A[32wid..][64] @ W[64][64]^T (both fp16) ----------
__device__ __forceinline__ void mma_layer(uint32_t sbAH, uint32_t sbWH,
                                          int wid, int lane, float acc[2][8][4]) {
    const int r7   = lane & 7;
    const int arow = r7 + (((lane >> 3) & 1) << 3);
    const int asel = lane >> 4;
    const int brow = r7 + ((lane >> 4) << 3);
    const int bsel = (lane >> 3) & 1;
#pragma unroll
    for (int ks = 0; ks < 4; ks++) {
        uint32_t ah[2][4];
#pragma unroll
        for (int mi = 0; mi < 2; mi++) {
            uint32_t off = (uint32_t)((32 * wid + mi * 16 + arow) * 128 +
                                      (((ks * 2 + asel) ^ r7) << 4));
            ldmx4(ah[mi][0], ah[mi][1], ah[mi][2], ah[mi][3], sbAH + off);
        }
#pragma unroll
        for (int p = 0; p < 4; p++) {
            uint32_t woff = (uint32_t)((p * 16 + brow) * 128 +
                                       (((ks * 2 + bsel) ^ r7) << 4));
            uint32_t bh0, bh1, bh2, bh3;
            ldmx4(bh0, bh1, bh2, bh3, sbWH + woff);
#pragma unroll
            for (int mi = 0; mi < 2; mi++) {
                MMA16816(acc[mi][2 * p],     ah[mi][0], ah[mi][1], ah[mi][2], ah[mi][3], bh0, bh1);
                MMA16816(acc[mi][2 * p + 1], ah[mi][0], ah[mi][1], ah[mi][2], ah[mi][3], bh2, bh3);
            }
        }
    }
}

// ---------------- kernel 2: HMMA edge MLP + segmented reduction (both scales) ----
#define EPB 128
#define X_IDX  0        // int2 sidx2[128] = 1024 B
#define X_W0T  1024
#define X_B0   2048
#define X_B1   2304
#define X_B2   2560
#define X_WT   2816
#define X_W1H  (X_WT + 0)
#define X_W2H  (X_WT + 8192)
#define X_AH   19200    // 16384 B, ends 35584
#define X_K    2816     // fp32 k buffer overlay (WT+AH dead), 128 x 264 B = 33792
#define SMEM_EDGE_BYTES 36608

__global__ __launch_bounds__(128, 4) void edge_kernel(
    const float* __restrict__ latc, const float* __restrict__ qc,
    const float* __restrict__ rnd,
    const int* __restrict__ src0, const int* __restrict__ qry0,
    const int* __restrict__ src1, const int* __restrict__ qry1,
    const float* __restrict__ Wk0, const float* __restrict__ bk0,
    const float* __restrict__ bk1, const float* __restrict__ bk2,
    int nb0, int E0, int E1)
{
    extern __shared__ char smc[];
    float* smf = (float*)smc;
    const uint32_t sb = smem_u32(smc);
    const int tid = threadIdx.x, wid = tid >> 5, lane = tid & 31;

    int scale, tile, E;
    const int *src, *qry;
    if ((int)blockIdx.x < nb0) { scale = 0; tile = blockIdx.x; src = src0; qry = qry0; E = E0; }
    else { scale = 1; tile = blockIdx.x - nb0; src = src1; qry = qry1; E = E1; }

    {
        const uint4* gw = (const uint4*)g_wt;
        uint4* sw = (uint4*)(smc + X_WT);
#pragma unroll
        for (int i = 0; i < 8; i++) sw[tid + 128 * i] = gw[tid + 128 * i];
    }
    for (int i = tid; i < 256; i += 128) smf[(X_W0T >> 2) + (i & 63) * 4 + (i >> 6)] = Wk0[i];
    if (tid < 64) {
        smf[(X_B0 >> 2) + tid] = bk0[tid];
        smf[(X_B1 >> 2) + tid] = bk1[tid];
        smf[(X_B2 >> 2) + tid] = bk2[tid];
    }

    const int e = tile * EPB + tid;
    int s = 0, q = -1;
    if (e < E) { s = src[e]; q = qry[e]; }
    int2* sidx2 = (int2*)(smc + X_IDX);
    sidx2[tid] = make_int2(s, q);
    float f0 = latc[2 * s], f1 = latc[2 * s + 1];
    float f2 = 0.f, f3 = 0.f;
    if (q >= 0) { f2 = qc[2 * q]; f3 = qc[2 * q + 1]; }
    __syncthreads();

    // layer 1: 4 -> 64 per-thread, gelu, fp16 -> A tile (own row)
    {
        const float4* w0 = (const float4*)(smc + X_W0T);
        const float* b0 = smf + (X_B0 >> 2);
#pragma unroll
        for (int c = 0; c < 8; c++) {
            float v[8];
#pragma unroll
            for (int jj = 0; jj < 8; jj++) {
                int j = c * 8 + jj;
                float4 w = w0[j];
                float a = b0[j];
                a = fmaf(f0, w.x, a); a = fmaf(f1, w.y, a);
                a = fmaf(f2, w.z, a); a = fmaf(f3, w.w, a);
                v[jj] = gelu_f(a);
            }
            uint32_t h[4];
#pragma unroll
            for (int m = 0; m < 4; m++) h[m] = pkhf(v[2 * m], v[2 * m + 1]);
            uint32_t off = (uint32_t)(tid * 128 + ((c ^ (tid & 7)) << 4));
            *(uint4*)(smc + X_AH + off) = make_uint4(h[0], h[1], h[2], h[3]);
        }
    }
    __syncwarp();

    float acc[2][8][4];
#pragma unroll
    for (int mi = 0; mi < 2; mi++)
#pragma unroll
        for (int ni = 0; ni < 8; ni++)
#pragma unroll
            for (int z = 0; z < 4; z++) acc[mi][ni][z] = 0.f;

    mma_layer(sb + X_AH, sb + X_W1H, wid, lane, acc);

    {
        const float* b1 = smf + (X_B1 >> 2);
        const int g = lane >> 2, t = lane & 3;
#pragma unroll
        for (int mi = 0; mi < 2; mi++) {
            int row0 = 32 * wid + mi * 16 + g;
#pragma unroll
            for (int ni = 0; ni < 8; ni++) {
                float2 bb = *(const float2*)(b1 + ni * 8 + t * 2);
                float v0 = gelu_f(acc[mi][ni][0] + bb.x);
                float v1 = gelu_f(acc[mi][ni][1] + bb.y);
                float v2 = gelu_f(acc[mi][ni][2] + bb.x);
                float v3 = gelu_f(acc[mi][ni][3] + bb.y);
                int r1 = row0 + 8;
                uint32_t offA = (uint32_t)(row0 * 128 + ((ni ^ (row0 & 7)) << 4) + t * 4);
                uint32_t offB = (uint32_t)(r1 * 128 + ((ni ^ (r1 & 7)) << 4) + t * 4);
                *(uint32_t*)(smc + X_AH + offA) = pkhf(v0, v1);
                *(uint32_t*)(smc + X_AH + offB) = pkhf(v2, v3);
                acc[mi][ni][0] = 0.f; acc[mi][ni][1] = 0.f;
                acc[mi][ni][2] = 0.f; acc[mi][ni][3] = 0.f;
            }
        }
    }
    __syncwarp();

    mma_layer(sb + X_AH, sb + X_W2H, wid, lane, acc);
    __syncthreads();   // WT/AH now dead everywhere; K buffer overlays them

    {
        const float* b2 = smf + (X_B2 >> 2);
        const int g = lane >> 2, t = lane & 3;
#pragma unroll
        for (int mi = 0; mi < 2; mi++) {
            int row0 = 32 * wid + mi * 16 + g;
#pragma unroll
            for (int ni = 0; ni < 8; ni++) {
                float2 bb = *(const float2*)(b2 + ni * 8 + t * 2);
                int colb = (ni * 8 + t * 2) * 4;
                *(float2*)(smc + X_K + row0 * 264 + colb) =
                    make_float2(acc[mi][ni][0] + bb.x, acc[mi][ni][1] + bb.y);
                *(float2*)(smc + X_K + (row0 + 8) * 264 + colb) =
                    make_float2(acc[mi][ni][2] + bb.x, acc[mi][ni][3] + bb.y);
            }
        }
    }
    __syncthreads();

    // phase B: segmented reduction, chunk-of-8 prefetch
    const int b  = wid;
    const int c2 = lane;
    const float* rb = rnd + (size_t)b * N_LAT * CIN + 2 * c2;
    float* accBase = g_acc + ((size_t)(scale * BB + b) * N_QRY) * CIN + 2 * c2;
    float* cntBase = g_cnt + scale * N_QRY;

    float ax = 0.f, ay = 0.f;
    int prevq = -1, run = 0;
#pragma unroll 1
    for (int base = 0; base < EPB; base += 8) {
        float2 rr[8], kk[8];
        int qv[8];
#pragma unroll
        for (int j = 0; j < 8; j++) {
            int2 sq = sidx2[base + j];
            qv[j] = sq.y;
            rr[j] = *(const float2*)(rb + (size_t)sq.x * CIN);
            kk[j] = *(const float2*)(smc + X_K + (base + j) * 264 + c2 * 8);
        }
#pragma unroll
        for (int j = 0; j < 8; j++) {
            int qq = qv[j];
            if (qq != prevq) {
                if (prevq >= 0) {
                    float* d = accBase + (size_t)prevq * CIN;
                    atomicAdd(d, ax);
                    atomicAdd(d + 1, ay);
                    if (tid == 0) atomicAdd(cntBase + prevq, (float)run);
                }
                ax = 0.f; ay = 0.f; run = 0; prevq = qq;
            }
            if (qq >= 0) {
                ax = fmaf(kk[j].x, rr[j].x, ax);
                ay = fmaf(kk[j].y, rr[j].y, ay);
                run++;
            }
        }
    }
    if (prevq >= 0) {
        float* d = accBase + (size_t)prevq * CIN;
        atomicAdd(d, ax);
        atomicAdd(d + 1, ay);
        if (tid == 0) atomicAdd(cntBase + prevq, (float)run);
    }
}

// ---------------- kernel 3: HMMA combine + projection MLP ------------------------
#define CM_WTH  0          // 32768 B Wp0^T fp16
#define CM_AH   32768      // 16384 B
#define CM_WP1  49152      // 4096 B (256 x float4)
#define CM_BP0  53248      // 1024 B
#define CM_BP1  54272      // 16 B
#define SMEM_COMB_BYTES 54288

__global__ __launch_bounds__(128) void combine_kernel(
    const float* __restrict__ bp0, const float* __restrict__ Wp1,
    const float* __restrict__ bp1, float* __restrict__ out)
{
    extern __shared__ char smc[];
    float* smf = (float*)smc;
    const uint32_t sb = smem_u32(smc);
    const int tid = threadIdx.x, wid = tid >> 5, lane = tid & 31;
    const int g = lane >> 2, t4 = lane & 3;

    {
        const uint4* gw = (const uint4*)g_wt2;
        uint4* sw = (uint4*)(smc + CM_WTH);
#pragma unroll
        for (int i = 0; i < 16; i++) sw[tid + 128 * i] = gw[tid + 128 * i];
    }
    for (int i = tid; i < 256; i += 128) ((uint4*)(smc + CM_WP1))[i] = ((const uint4*)Wp1)[i];
    if (tid < 64) ((uint4*)(smc + CM_BP0))[tid] = ((const uint4*)bp0)[tid];
    if (tid < 4) smf[(CM_BP1 >> 2) + tid] = bp1[tid];

    const int R = blockIdx.x * 128;
    {
        const size_t ss = (size_t)BB * N_QRY * CIN;
#pragma unroll 2
        for (int i = 0; i < 32; i++) {
            int lr = wid * 32 + i;
            int r = R + lr;
            int q = r & (N_QRY - 1);
            int b = r >> 14;
            float i0 = __fdividef(g_w[2 * q],     fmaxf(g_cnt[q], 1.f));
            float i1 = __fdividef(g_w[2 * q + 1], fmaxf(g_cnt[N_QRY + q], 1.f));
            size_t base0 = ((size_t)b * N_QRY + q) * CIN;
            size_t base1 = base0 + ss;
            float v  = fmaf(i0, g_acc[base0 + lane],      i1 * g_acc[base1 + lane]);
            float v2 = fmaf(i0, g_acc[base0 + lane + 32], i1 * g_acc[base1 + lane + 32]);
            uint32_t o1 = (uint32_t)(lr * 128 + (((lane >> 3) ^ (lr & 7)) << 4) + (lane & 7) * 2);
            uint32_t o2 = (uint32_t)(lr * 128 + ((((lane + 32) >> 3) ^ (lr & 7)) << 4) + (lane & 7) * 2);
            *(__half*)(smc + CM_AH + o1) = __float2half_rn(v);
            *(__half*)(smc + CM_AH + o2) = __float2half_rn(v2);
        }
    }
    __syncthreads();

    float o_[4][4];
#pragma unroll
    for (int a = 0; a < 4; a++)
#pragma unroll
        for (int c = 0; c < 4; c++) o_[a][c] = 0.f;

    float acc[2][8][4];
    const float* bp0s = smf + (CM_BP0 >> 2);
    const float4* wp1s = (const float4*)(smc + CM_WP1);

#pragma unroll 1
    for (int c = 0; c < 4; c++) {
#pragma unroll
        for (int mi = 0; mi < 2; mi++)
#pragma unroll
            for (int ni = 0; ni < 8; ni++)
#pragma unroll
                for (int z = 0; z < 4; z++) acc[mi][ni][z] = 0.f;

        mma_layer(sb + CM_AH, sb + CM_WTH + c * 8192, wid, lane, acc);

#pragma unroll
        for (int ni = 0; ni < 8; ni++) {
            int col0 = c * 64 + ni * 8 + t4 * 2;
            float2 bb = *(const float2*)(bp0s + col0);
            float4 wA = wp1s[col0];
            float4 wB = wp1s[col0 + 1];
#pragma unroll
            for (int mi = 0; mi < 2; mi++) {
                float v0 = gelu_f(acc[mi][ni][0] + bb.x);
                float v1 = gelu_f(acc[mi][ni][1] + bb.y);
                float v2 = gelu_f(acc[mi][ni][2] + bb.x);
                float v3 = gelu_f(acc[mi][ni][3] + bb.y);
                float* oa = o_[mi * 2];
                oa[0] = fmaf(v0, wA.x, oa[0]); oa[1] = fmaf(v0, wA.y, oa[1]);
                oa[2] = fmaf(v0, wA.z, oa[2]); oa[3] = fmaf(v0, wA.w, oa[3]);
                oa[0] = fmaf(v1, wB.x, oa[0]); oa[1] = fmaf(v1, wB.y, oa[1]);
                oa[2] = fmaf(v1, wB.z, oa[2]); oa[3] = fmaf(v1, wB.w, oa[3]);
                float* ob = o_[mi * 2 + 1];
                ob[0] = fmaf(v2, wA.x, ob[0]); ob[1] = fmaf(v2, wA.y, ob[1]);
                ob[2] = fmaf(v2, wA.z, ob[2]); ob[3] = fmaf(v2, wA.w, ob[3]);
                ob[0] = fmaf(v3, wB.x, ob[0]); ob[1] = fmaf(v3, wB.y, ob[1]);
                ob[2] = fmaf(v3, wB.z, ob[2]); ob[3] = fmaf(v3, wB.w, ob[3]);
            }
        }
    }

#pragma unroll
    for (int rI = 0; rI < 4; rI++)
#pragma unroll
        for (int cc = 0; cc < 4; cc++) {
            float v = o_[rI][cc];
            v += __shfl_xor_sync(0xffffffffu, v, 1);
            v += __shfl_xor_sync(0xffffffffu, v, 2);
            o_[rI][cc] = v;
        }
    if (t4 == 0) {
        const float* b1 = smf + (CM_BP1 >> 2);
#pragma unroll
        for (int rI = 0; rI < 4; rI++) {
            int row = R + 32 * wid + g + (rI >> 1) * 16 + (rI & 1) * 8;
            float4 r4;
            r4.x = o_[rI][0] + b1[0];
            r4.y = o_[rI][1] + b1[1];
            r4.z = o_[rI][2] + b1[2];
            r4.w = o_[rI][3] + b1[3];
            ((float4*)out)[row] = r4;
        }
    }
}

// ---------------- launch ---------------------------------------------------------
extern "C" void kernel_launch(void* const* d_in, const int* in_sizes, int n_in,
                              void* d_out, int out_size)
{
    const float* latc = (const float*)d_in[0];
    const float* rnd  = (const float*)d_in[1];
    const float* qc   = (const float*)d_in[2];
    const int*   src0 = (const int*)d_in[3];
    const int*   qry0 = (const int*)d_in[4];
    const int*   src1 = (const int*)d_in[5];
    const int*   qry1 = (const int*)d_in[6];
    const float* Wk0  = (const float*)d_in[7];
    const float* bk0  = (const float*)d_in[8];
    const float* Wk1  = (const float*)d_in[9];
    const float* bk1  = (const float*)d_in[10];
    const float* Wk2  = (const float*)d_in[11];
    const float* bk2  = (const float*)d_in[12];
    const float* Wsw0 = (const float*)d_in[13];
    const float* bsw0 = (const float*)d_in[14];
    const float* Wsw1 = (const float*)d_in[15];
    const float* bsw1 = (const float*)d_in[16];
    const float* Wp0  = (const float*)d_in[17];
    const float* bp0  = (const float*)d_in[18];
    const float* Wp1  = (const float*)d_in[19];
    const float* bp1  = (const float*)d_in[20];

    const int E0 = in_sizes[3];
    const int E1 = in_sizes[5];
    const int nb0 = (E0 + EPB - 1) / EPB;
    const int nb1 = (E1 + EPB - 1) / EPB;

    cudaFuncSetAttribute(edge_kernel,    cudaFuncAttributeMaxDynamicSharedMemorySize, SMEM_EDGE_BYTES);
    cudaFuncSetAttribute(combine_kernel, cudaFuncAttributeMaxDynamicSharedMemorySize, SMEM_COMB_BYTES);

    setup_kernel<<<1104, 256>>>(Wk1, Wk2, Wp0, qc, Wsw0, bsw0, Wsw1, bsw1);
    edge_kernel<<<nb0 + nb1, 128, SMEM_EDGE_BYTES>>>(latc, qc, rnd,
                                                     src0, qry0, src1, qry1,
                                                     Wk0, bk0, bk1, bk2, nb0, E0, E1);
    combine_kernel<<<512, 128, SMEM_COMB_BYTES>>>(bp0, Wp1, bp1, (float*)d_out);
}